// round 7
// baseline (speedup 1.0000x reference)
#include <cuda_runtime.h>
#include <cuda_bf16.h>
#include <cstdint>

#define CC 256
#define NN 4096
#define BB 8

// ---------------- device globals (no runtime allocs allowed) ----------------
static __device__ __nv_bfloat16 g_Ah[CC * CC];      // A hi  [d][c]
static __device__ __nv_bfloat16 g_Al[CC * CC];      // A lo
static __device__ __nv_bfloat16 g_Xt_hi[(size_t)BB * NN * CC];  // X^T hi [b][n][c]
static __device__ __nv_bfloat16 g_Xt_lo[(size_t)BB * NN * CC];
static __device__ __nv_bfloat16 g_Zt_hi[(size_t)BB * NN * CC];  // Z^T hi [b][n][d]
static __device__ __nv_bfloat16 g_Zt_lo[(size_t)BB * NN * CC];
// split-softmax partials: [b*32+nt][mq][row]
static __device__ float g_pm[(size_t)BB * 32 * 4 * 128];
static __device__ float g_ps[(size_t)BB * 32 * 4 * 128];
static __device__ float g_dlog[(size_t)BB * 32 * 128];

// ---------------- helpers ----------------
__device__ __forceinline__ float fexp2(float x) {
    float y;
    asm("ex2.approx.ftz.f32 %0, %1;" : "=f"(y) : "f"(x));
    return y;
}
__device__ __forceinline__ uint32_t smem_u32(const void* p) {
    uint32_t a;
    asm("{ .reg .u64 t; cvta.to.shared.u64 t, %1; cvt.u32.u64 %0, t; }" : "=r"(a) : "l"(p));
    return a;
}
#define SWZ(o) ((o) ^ (((o) >> 3) & 0x70))

#define CP16(dst, src) \
    asm volatile("cp.async.cg.shared.global [%0], [%1], 16;" :: "r"(dst), "l"(src) : "memory")
#define CP_COMMIT() asm volatile("cp.async.commit_group;" ::: "memory")
#define CP_WAIT0()  asm volatile("cp.async.wait_group 0;" ::: "memory")

__device__ __forceinline__ void ldsm4(uint32_t* r, uint32_t a) {
    asm volatile("ldmatrix.sync.aligned.m8n8.x4.shared.b16 {%0,%1,%2,%3}, [%4];"
        : "=r"(r[0]), "=r"(r[1]), "=r"(r[2]), "=r"(r[3]) : "r"(a));
}
__device__ __forceinline__ void mma16816(float* d, const uint32_t* a, const uint32_t* b) {
    asm volatile("mma.sync.aligned.m16n8k16.row.col.f32.bf16.bf16.f32 "
        "{%0,%1,%2,%3}, {%4,%5,%6,%7}, {%8,%9}, {%0,%1,%2,%3};"
        : "+f"(d[0]), "+f"(d[1]), "+f"(d[2]), "+f"(d[3])
        : "r"(a[0]), "r"(a[1]), "r"(a[2]), "r"(a[3]), "r"(b[0]), "r"(b[1]));
}
__device__ __forceinline__ uint32_t pack_bf16x2(__nv_bfloat16 a, __nv_bfloat16 b) {
    return (uint32_t)__bfloat16_as_ushort(a) | ((uint32_t)__bfloat16_as_ushort(b) << 16);
}

// ---------------------------------------------------------------------------
// A[d][c] = log2e * sum_e Wq[e][c] * Wk[e][d], stored as bf16 hi/lo
// ---------------------------------------------------------------------------
__global__ void k_prepA(const float* __restrict__ Wq, const float* __restrict__ Wk) {
    const float LOG2E = 1.4426950408889634f;
    int c = blockIdx.x * 32 + threadIdx.x;
    int d = blockIdx.y * 8 + threadIdx.y;
    float s0 = 0.f, s1 = 0.f;
#pragma unroll 8
    for (int e = 0; e < CC; e += 2) {
        s0 = fmaf(Wq[e * CC + c], Wk[e * CC + d], s0);
        s1 = fmaf(Wq[(e + 1) * CC + c], Wk[(e + 1) * CC + d], s1);
    }
    float v = (s0 + s1) * LOG2E;
    __nv_bfloat16 h = __float2bfloat16(v);
    g_Ah[d * CC + c] = h;
    g_Al[d * CC + c] = __float2bfloat16(v - __bfloat162float(h));
}

// ---------------------------------------------------------------------------
// Transpose + bf16 hi/lo split: X[b][c][n] -> Xt_hi/lo[b][n][c]
// ---------------------------------------------------------------------------
__global__ __launch_bounds__(256) void k_prep(const float* __restrict__ X) {
    __shared__ float s[32][33];
    const int b = blockIdx.z, c0 = blockIdx.y * 32, n0 = blockIdx.x * 32;
    const int tx = threadIdx.x, ty = threadIdx.y;
    const float* Xb = X + (size_t)b * CC * NN;
#pragma unroll
    for (int i = 0; i < 4; i++)
        s[ty + 8 * i][tx] = Xb[(size_t)(c0 + ty + 8 * i) * NN + n0 + tx];
    __syncthreads();
    const size_t base = (size_t)b * NN * CC;
#pragma unroll
    for (int i = 0; i < 4; i++) {
        int n = n0 + ty + 8 * i;
        float v = s[tx][ty + 8 * i];
        __nv_bfloat16 h = __float2bfloat16(v);
        g_Xt_hi[base + (size_t)n * CC + c0 + tx] = h;
        g_Xt_lo[base + (size_t)n * CC + c0 + tx] =
            __float2bfloat16(v - __bfloat162float(h));
    }
}

// ---------------------------------------------------------------------------
// k_Zt: Zt[n][d] = sum_c Xt[n][c] * A[d][c]   (3-term bf16 split, mma.sync)
// ---------------------------------------------------------------------------
__global__ __launch_bounds__(256, 1) void k_Zt() {
    extern __shared__ char smem[];
    const uint32_t sb = smem_u32(smem);
    const int tid = threadIdx.x;
    const int wid = tid >> 5, lane = tid & 31;
    const int g = lane >> 2;
    const int n0 = blockIdx.x << 7;
    const int d0 = blockIdx.y << 7;
    const int b = blockIdx.z;
    const size_t bbase = (size_t)b * NN * CC;
    const char* Xsrc[2] = {(const char*)(g_Xt_hi + bbase), (const char*)(g_Xt_lo + bbase)};
    const char* Asrc[2] = {(const char*)g_Ah, (const char*)g_Al};

    const int aRow = wid * 16 + (lane & 15);
    const uint32_t aOff = (uint32_t)(aRow * 128);
    const uint32_t aSwz = (uint32_t)((aRow * 16) & 0x70);
    const int aColX = (lane >> 4) << 4;
    const int bRowOff = (lane & 7) + ((lane >> 4) & 1) * 8;
    const int bColX = ((lane >> 3) & 1) << 4;

    float acc[16][4];
#pragma unroll
    for (int i = 0; i < 16; i++)
#pragma unroll
        for (int j = 0; j < 4; j++) acc[i][j] = 0.f;

#pragma unroll
    for (int t = 0; t < 16; t++) {
        int o = tid + t * 256;
        int role = o >> 10, r = (o >> 3) & 127, j = o & 7;
        const char* src = (role < 2)
            ? Xsrc[role] + ((size_t)(n0 + r) * CC) * 2 + j * 16
            : Asrc[role - 2] + ((size_t)(d0 + r) * CC) * 2 + j * 16;
        uint32_t dst = sb + (uint32_t)role * 16384u + SWZ((uint32_t)(r * 128 + j * 16));
        CP16(dst, src);
    }
    CP_COMMIT();

#pragma unroll 1
    for (int cc = 0; cc < 4; cc++) {
        const int buf = cc & 1;
        CP_WAIT0();
        __syncthreads();
        if (cc < 3) {
            const int cn = cc + 1, bn = buf ^ 1;
#pragma unroll
            for (int t = 0; t < 16; t++) {
                int o = tid + t * 256;
                int role = o >> 10, r = (o >> 3) & 127, j = o & 7;
                const char* src = (role < 2)
                    ? Xsrc[role] + ((size_t)(n0 + r) * CC + cn * 64) * 2 + j * 16
                    : Asrc[role - 2] + ((size_t)(d0 + r) * CC + cn * 64) * 2 + j * 16;
                uint32_t dst = sb + (uint32_t)(bn * 4 + role) * 16384u +
                               SWZ((uint32_t)(r * 128 + j * 16));
                CP16(dst, src);
            }
        }
        CP_COMMIT();

        const uint32_t xh = sb + (uint32_t)(buf * 4 + 0) * 16384u;
        const uint32_t xl = xh + 16384u;
        const uint32_t ah = sb + (uint32_t)(buf * 4 + 2) * 16384u;
        const uint32_t al = ah + 16384u;
#pragma unroll
        for (int ks = 0; ks < 4; ks++) {
            const int cb = ks * 32;
            uint32_t Ah[4], Al[4];
            uint32_t aoff = aOff + (uint32_t)((cb + aColX) ^ aSwz);
            ldsm4(Ah, xh + aoff);
            ldsm4(Al, xl + aoff);
#pragma unroll
            for (int j2 = 0; j2 < 8; j2++) {
                uint32_t Bh[4], Bl[4];
                int brow = j2 * 16 + bRowOff;
                uint32_t boff = (uint32_t)(brow * 128) +
                                (uint32_t)((cb + bColX) ^ ((brow * 16) & 0x70));
                ldsm4(Bh, ah + boff);
                ldsm4(Bl, al + boff);
                mma16816(acc[j2 * 2],     Ah, Bh);
                mma16816(acc[j2 * 2 + 1], Ah, Bh + 2);
                mma16816(acc[j2 * 2],     Ah, Bl);
                mma16816(acc[j2 * 2 + 1], Ah, Bl + 2);
                mma16816(acc[j2 * 2],     Al, Bh);
                mma16816(acc[j2 * 2 + 1], Al, Bh + 2);
            }
        }
    }

    char* Zh = (char*)(g_Zt_hi + bbase);
    char* Zl = (char*)(g_Zt_lo + bbase);
#pragma unroll
    for (int h = 0; h < 2; h++) {
        int n = n0 + wid * 16 + h * 8 + g;
#pragma unroll
        for (int bt = 0; bt < 16; bt++) {
            float v0 = acc[bt][2 * h], v1 = acc[bt][2 * h + 1];
            __nv_bfloat16 h0 = __float2bfloat16(v0);
            __nv_bfloat16 h1 = __float2bfloat16(v1);
            __nv_bfloat16 l0 = __float2bfloat16(v0 - __bfloat162float(h0));
            __nv_bfloat16 l1 = __float2bfloat16(v1 - __bfloat162float(h1));
            size_t off = ((size_t)n * CC + d0 + bt * 8 + 2 * (lane & 3)) * 2;
            *(uint32_t*)(Zh + off) = pack_bf16x2(h0, h1);
            *(uint32_t*)(Zl + off) = pack_bf16x2(l0, l1);
        }
    }
}

// ---------------------------------------------------------------------------
// k_part: grid B*32*4 (b, nt, mq), 512 threads, 16 warps in 4x4 grid,
// warp tile 32 rows x 64 cols -> CTA tile 128 x 256 (one "pair-tile").
// mq quarter = 4 pair-tiles; K streamed in chunks of 32 (G = 32 iters).
// Z persistent (128KB, SW128). X chunk buffers: 256 rows x 64B data at
// stride 80B (pad-swizzle, conflict-optimal ldsm), x {hi,lo} = 40KB,
// double-buffered. Softmax boundary every 8 chunks (per pair-tile).
// ---------------------------------------------------------------------------
#define SM_ZS 0u
#define SM_XS 131072u
#define XBUF  40960u
#define XHALF 20480u
#define SM_TOTAL (131072 + 2 * 40960)

__global__ __launch_bounds__(512, 1) void k_part() {
    extern __shared__ char smem[];
    const uint32_t sb = smem_u32(smem);
    const int tid = threadIdx.x;
    const int wid = tid >> 5, lane = tid & 31;
    const int wr = wid >> 2, wc = wid & 3;
    const int q = lane >> 2;
    const int bx = blockIdx.x;
    const int b = bx >> 7;
    const int nt = (bx >> 2) & 31;
    const int mq = bx & 3;
    const int n0 = nt << 7;
    const size_t bbase = (size_t)b * NN * CC;
    const char* Zsrc[2] = {(const char*)(g_Zt_hi + bbase), (const char*)(g_Zt_lo + bbase)};
    const char* Xsrc[2] = {(const char*)(g_Xt_hi + bbase), (const char*)(g_Xt_lo + bbase)};

    const int aColX = (lane >> 4) << 4;
    const int bRowL = (lane & 7) + ((lane >> 4) & 1) * 8;   // n-row within n16
    const int bSegX = ((lane >> 3) & 1) << 4;               // k8 half of k16

    // ---- prologue: Z (8 tiles, SW128) + X chunk0 into buf0 ----
#pragma unroll
    for (int t = 0; t < 16; t++) {
        int o = tid + t * 512;
        int ch = o >> 11, hs = (o >> 10) & 1, r = (o >> 3) & 127, j = o & 7;
        const char* src = Zsrc[hs] + ((size_t)(n0 + r) * CC + ch * 64) * 2 + j * 16;
        uint32_t dst = sb + SM_ZS + (uint32_t)(ch * 2 + hs) * 16384u +
                       SWZ((uint32_t)(r * 128 + j * 16));
        CP16(dst, src);
    }
#pragma unroll
    for (int t = 0; t < 4; t++) {
        int o = tid + t * 512;
        int hs = o >> 10, rem = o & 1023, r = rem >> 2, seg = rem & 3;
        const char* src = Xsrc[hs] + (size_t)(mq * 1024 + r) * (CC * 2) + seg * 16;
        uint32_t dst = sb + SM_XS + (uint32_t)hs * XHALF +
                       (uint32_t)(r * 80 + seg * 16);
        CP16(dst, src);
    }
    CP_COMMIT();

    float acc[2][8][4];
#pragma unroll
    for (int i = 0; i < 2; i++)
#pragma unroll
        for (int j = 0; j < 8; j++)
#pragma unroll
            for (int k = 0; k < 4; k++) acc[i][j][k] = 0.f;
    float mrun[2][2], rsum[2][2];
#pragma unroll
    for (int i = 0; i < 2; i++)
#pragma unroll
        for (int j = 0; j < 2; j++) { mrun[i][j] = -3.0e38f; rsum[i][j] = 0.f; }

#pragma unroll 1
    for (int G = 0; G < 32; G++) {
        const int pt = G >> 3, kc = G & 7, buf = G & 1;
        CP_WAIT0();              // chunk G (issued last iter) has landed
        __syncthreads();

        // prefetch chunk G+1 into other buffer (consumed last iter, synced)
        if (G < 31) {
            const int Gn = G + 1;
            const int m0n = mq * 1024 + (Gn >> 3) * 256, kcn = Gn & 7;
#pragma unroll
            for (int t = 0; t < 4; t++) {
                int o = tid + t * 512;
                int hs = o >> 10, rem = o & 1023, r = rem >> 2, seg = rem & 3;
                const char* src = Xsrc[hs] +
                    (size_t)(m0n + r) * (CC * 2) + kcn * 64 + seg * 16;
                uint32_t dst = sb + SM_XS + (uint32_t)(buf ^ 1) * XBUF +
                               (uint32_t)hs * XHALF + (uint32_t)(r * 80 + seg * 16);
                CP16(dst, src);
            }
        }
        CP_COMMIT();

        // ---- MMA: K-chunk of 32 (2 k16 sub-steps) ----
        const uint32_t zb = sb + SM_ZS + (uint32_t)(kc >> 1) * 32768u;
        const uint32_t xb = sb + SM_XS + (uint32_t)buf * XBUF;
        const int cb0 = (kc & 1) * 64;
#pragma unroll
        for (int ks = 0; ks < 2; ks++) {
            const int cbk = cb0 + ks * 32;
            uint32_t Ah[2][4], Al[2][4];
#pragma unroll
            for (int rb = 0; rb < 2; rb++) {
                int row = wr * 32 + rb * 16 + (lane & 15);
                uint32_t off = (uint32_t)(row * 128) +
                               (uint32_t)((cbk + aColX) ^ ((row * 16) & 0x70));
                ldsm4(Ah[rb], zb + off);
                ldsm4(Al[rb], zb + 16384u + off);
            }
#pragma unroll
            for (int cs = 0; cs < 4; cs++) {
                uint32_t Bh[4], Bl[4];
                int row = wc * 64 + cs * 16 + bRowL;
                uint32_t boff = (uint32_t)(row * 80 + ks * 32) + (uint32_t)bSegX;
                ldsm4(Bh, xb + boff);
                ldsm4(Bl, xb + XHALF + boff);
                const int j0 = cs * 2;
                mma16816(acc[0][j0],     Ah[0], Bh);
                mma16816(acc[0][j0 + 1], Ah[0], Bh + 2);
                mma16816(acc[1][j0],     Ah[1], Bh);
                mma16816(acc[1][j0 + 1], Ah[1], Bh + 2);
                mma16816(acc[0][j0],     Ah[0], Bl);
                mma16816(acc[0][j0 + 1], Ah[0], Bl + 2);
                mma16816(acc[1][j0],     Ah[1], Bl);
                mma16816(acc[1][j0 + 1], Ah[1], Bl + 2);
                mma16816(acc[0][j0],     Al[0], Bh);
                mma16816(acc[0][j0 + 1], Al[0], Bh + 2);
                mma16816(acc[1][j0],     Al[1], Bh);
                mma16816(acc[1][j0 + 1], Al[1], Bh + 2);
            }
        }

        // ---- pair-tile boundary (every 8 chunks): online softmax ----
        if (kc == 7) {
            // all warps must finish ldsm of buf before scratch scrawl
            __syncthreads();
            float* pmax = (float*)(smem + SM_XS + (uint32_t)buf * XBUF);
            float* psum = pmax + 512;

#pragma unroll
            for (int rb = 0; rb < 2; rb++)
#pragma unroll
                for (int rh = 0; rh < 2; rh++) {
                    float tm = -3.0e38f;
#pragma unroll
                    for (int j = 0; j < 8; j++)
                        tm = fmaxf(tm, fmaxf(acc[rb][j][2 * rh], acc[rb][j][2 * rh + 1]));
                    tm = fmaxf(tm, __shfl_xor_sync(0xffffffffu, tm, 1));
                    tm = fmaxf(tm, __shfl_xor_sync(0xffffffffu, tm, 2));
                    float ps = 0.f;
#pragma unroll
                    for (int j = 0; j < 8; j++) {
                        ps += fexp2(acc[rb][j][2 * rh] - tm);
                        ps += fexp2(acc[rb][j][2 * rh + 1] - tm);
                    }
                    ps += __shfl_xor_sync(0xffffffffu, ps, 1);
                    ps += __shfl_xor_sync(0xffffffffu, ps, 2);
                    if ((lane & 3) == 0) {
                        int rl = wr * 32 + rb * 16 + rh * 8 + q;
                        pmax[wc * 128 + rl] = tm;
                        psum[wc * 128 + rl] = ps;
                    }
                }
            // diag capture: rows n0..n0+127 fall in this pair-tile iff
            // mq==nt>>3 && pt==(nt>>1)&3; col = (nt&1)*128 + rl.
            if (mq == (nt >> 3) && pt == ((nt >> 1) & 3) &&
                wc == ((nt & 1) * 2 + (wr >> 1)) && ((lane & 3) == (q >> 1))) {
#pragma unroll
                for (int rb = 0; rb < 2; rb++)
#pragma unroll
                    for (int rh = 0; rh < 2; rh++) {
                        int cs = (wr & 1) * 2 + rb;
                        int rl = wr * 32 + rb * 16 + rh * 8 + q;
                        g_dlog[(size_t)(b * 32 + nt) * 128 + rl] =
                            acc[rb][cs * 2 + rh][2 * rh + (q & 1)];
                    }
            }
            __syncthreads();
            // replicated combine across the 4 wc partials
#pragma unroll
            for (int rb = 0; rb < 2; rb++)
#pragma unroll
                for (int rh = 0; rh < 2; rh++) {
                    int rl = wr * 32 + rb * 16 + rh * 8 + q;
                    float mn = mrun[rb][rh];
#pragma unroll
                    for (int j = 0; j < 4; j++) mn = fmaxf(mn, pmax[j * 128 + rl]);
                    float rs = rsum[rb][rh] * fexp2(mrun[rb][rh] - mn);
#pragma unroll
                    for (int j = 0; j < 4; j++)
                        rs += fexp2(pmax[j * 128 + rl] - mn) * psum[j * 128 + rl];
                    mrun[rb][rh] = mn;
                    rsum[rb][rh] = rs;
                }
#pragma unroll
            for (int i = 0; i < 2; i++)
#pragma unroll
                for (int j = 0; j < 8; j++)
#pragma unroll
                    for (int k = 0; k < 4; k++) acc[i][j][k] = 0.f;
        }
    }

    // write partial state
    if (wc == 0 && (lane & 3) == 0) {
#pragma unroll
        for (int rb = 0; rb < 2; rb++)
#pragma unroll
            for (int rh = 0; rh < 2; rh++) {
                int rl = wr * 32 + rb * 16 + rh * 8 + q;
                g_pm[(size_t)bx * 128 + rl] = mrun[rb][rh];
                g_ps[(size_t)bx * 128 + rl] = rsum[rb][rh];
            }
    }
}

// ---------------------------------------------------------------------------
// k_final: combine 4 partials -> diag; out[b][c][n0..] = X * diag
// ---------------------------------------------------------------------------
__global__ __launch_bounds__(512) void k_final(const float* __restrict__ X,
                                               float* __restrict__ out) {
    __shared__ float sdiag[128];
    const int bx = blockIdx.x;
    const int b = bx >> 5, nt = bx & 31;
    const int n0 = nt << 7;
    const int tid = threadIdx.x;

    if (tid < 128) {
        float pm[4];
        float M = -3.0e38f;
#pragma unroll
        for (int qd = 0; qd < 4; qd++) {
            pm[qd] = g_pm[((size_t)bx * 4 + qd) * 128 + tid];
            M = fmaxf(M, pm[qd]);
        }
        float S = 0.f;
#pragma unroll
        for (int qd = 0; qd < 4; qd++)
            S += g_ps[((size_t)bx * 4 + qd) * 128 + tid] * fexp2(pm[qd] - M);
        sdiag[tid] = fexp2(g_dlog[(size_t)bx * 128 + tid] - M) / S *
                     (1.0f / (1.0f + 1e-8f));
    }
    __syncthreads();

    const float* Xb = X + (size_t)b * CC * NN;
    float* Ob = out + (size_t)b * CC * NN;
#pragma unroll 4
    for (int t = 0; t < 16; t++) {
        int f = tid + t * 512;
        int row = f >> 5;
        int c4 = (f & 31) << 2;
        float4 v = *(const float4*)&Xb[(size_t)row * NN + n0 + c4];
        float4 dv = *(const float4*)&sdiag[c4];
        v.x *= dv.x; v.y *= dv.y; v.z *= dv.z; v.w *= dv.w;
        *(float4*)&Ob[(size_t)row * NN + n0 + c4] = v;
    }
}

// ---------------------------------------------------------------------------
extern "C" void kernel_launch(void* const* d_in, const int* in_sizes, int n_in,
                              void* d_out, int out_size) {
    const float* X  = (const float*)d_in[0];
    const float* Wq = (const float*)d_in[1];
    const float* Wk = (const float*)d_in[2];
    float* out = (float*)d_out;

    cudaFuncSetAttribute(k_Zt, cudaFuncAttributeMaxDynamicSharedMemorySize, 131072);
    cudaFuncSetAttribute(k_part, cudaFuncAttributeMaxDynamicSharedMemorySize, SM_TOTAL);

    k_prepA<<<dim3(8, 32), dim3(32, 8)>>>(Wq, Wk);
    k_prep<<<dim3(NN / 32, CC / 32, BB), dim3(32, 8)>>>(X);
    k_Zt<<<dim3(32, 2, BB), 256, 131072>>>();
    k_part<<<BB * 32 * 4, 512, SM_TOTAL>>>();
    k_final<<<BB * 32, 512>>>(X, out);
}

// round 9
// speedup vs baseline: 1.8532x; 1.8532x over previous
#include <cuda_runtime.h>
#include <cuda_bf16.h>
#include <cstdint>

#define CC 256
#define NN 4096
#define BB 8

// ---------------- device globals (no runtime allocs allowed) ----------------
static __device__ __nv_bfloat16 g_Ah[CC * CC];      // A hi  [d][c]
static __device__ __nv_bfloat16 g_Al[CC * CC];      // A lo
static __device__ __nv_bfloat16 g_Xt_hi[(size_t)BB * NN * CC];  // X^T hi [b][n][c]
static __device__ __nv_bfloat16 g_Xt_lo[(size_t)BB * NN * CC];
static __device__ __nv_bfloat16 g_Zt_hi[(size_t)BB * NN * CC];  // Z^T hi [b][n][d]
static __device__ __nv_bfloat16 g_Zt_lo[(size_t)BB * NN * CC];
// split-softmax partials: [b*32+nt][mq][row]
static __device__ float g_pm[(size_t)BB * 32 * 4 * 128];
static __device__ float g_ps[(size_t)BB * 32 * 4 * 128];
static __device__ float g_dlog[(size_t)BB * 32 * 128];

// ---------------- helpers ----------------
__device__ __forceinline__ float fexp2(float x) {
    float y;
    asm("ex2.approx.ftz.f32 %0, %1;" : "=f"(y) : "f"(x));
    return y;
}
__device__ __forceinline__ uint32_t smem_u32(const void* p) {
    uint32_t a;
    asm("{ .reg .u64 t; cvta.to.shared.u64 t, %1; cvt.u32.u64 %0, t; }" : "=r"(a) : "l"(p));
    return a;
}
#define SWZ(o) ((o) ^ (((o) >> 3) & 0x70))

#define CP16(dst, src) \
    asm volatile("cp.async.cg.shared.global [%0], [%1], 16;" :: "r"(dst), "l"(src) : "memory")
#define CP_COMMIT() asm volatile("cp.async.commit_group;" ::: "memory")
#define CP_WAIT0()  asm volatile("cp.async.wait_group 0;" ::: "memory")
#define CP_WAIT1()  asm volatile("cp.async.wait_group 1;" ::: "memory")

__device__ __forceinline__ void ldsm4(uint32_t* r, uint32_t a) {
    asm volatile("ldmatrix.sync.aligned.m8n8.x4.shared.b16 {%0,%1,%2,%3}, [%4];"
        : "=r"(r[0]), "=r"(r[1]), "=r"(r[2]), "=r"(r[3]) : "r"(a));
}
__device__ __forceinline__ void mma16816(float* d, const uint32_t* a, const uint32_t* b) {
    asm volatile("mma.sync.aligned.m16n8k16.row.col.f32.bf16.bf16.f32 "
        "{%0,%1,%2,%3}, {%4,%5,%6,%7}, {%8,%9}, {%0,%1,%2,%3};"
        : "+f"(d[0]), "+f"(d[1]), "+f"(d[2]), "+f"(d[3])
        : "r"(a[0]), "r"(a[1]), "r"(a[2]), "r"(a[3]), "r"(b[0]), "r"(b[1]));
}
__device__ __forceinline__ uint32_t pack_bf16x2(__nv_bfloat16 a, __nv_bfloat16 b) {
    return (uint32_t)__bfloat16_as_ushort(a) | ((uint32_t)__bfloat16_as_ushort(b) << 16);
}

// ---------------------------------------------------------------------------
// A[d][c] = log2e * sum_e Wq[e][c] * Wk[e][d], stored as bf16 hi/lo
// ---------------------------------------------------------------------------
__global__ void k_prepA(const float* __restrict__ Wq, const float* __restrict__ Wk) {
    const float LOG2E = 1.4426950408889634f;
    int c = blockIdx.x * 32 + threadIdx.x;
    int d = blockIdx.y * 8 + threadIdx.y;
    float s0 = 0.f, s1 = 0.f;
#pragma unroll 8
    for (int e = 0; e < CC; e += 2) {
        s0 = fmaf(Wq[e * CC + c], Wk[e * CC + d], s0);
        s1 = fmaf(Wq[(e + 1) * CC + c], Wk[(e + 1) * CC + d], s1);
    }
    float v = (s0 + s1) * LOG2E;
    __nv_bfloat16 h = __float2bfloat16(v);
    g_Ah[d * CC + c] = h;
    g_Al[d * CC + c] = __float2bfloat16(v - __bfloat162float(h));
}

// ---------------------------------------------------------------------------
// Transpose + bf16 hi/lo split: X[b][c][n] -> Xt_hi/lo[b][n][c]
// ---------------------------------------------------------------------------
__global__ __launch_bounds__(256) void k_prep(const float* __restrict__ X) {
    __shared__ float s[32][33];
    const int b = blockIdx.z, c0 = blockIdx.y * 32, n0 = blockIdx.x * 32;
    const int tx = threadIdx.x, ty = threadIdx.y;
    const float* Xb = X + (size_t)b * CC * NN;
#pragma unroll
    for (int i = 0; i < 4; i++)
        s[ty + 8 * i][tx] = Xb[(size_t)(c0 + ty + 8 * i) * NN + n0 + tx];
    __syncthreads();
    const size_t base = (size_t)b * NN * CC;
#pragma unroll
    for (int i = 0; i < 4; i++) {
        int n = n0 + ty + 8 * i;
        float v = s[tx][ty + 8 * i];
        __nv_bfloat16 h = __float2bfloat16(v);
        g_Xt_hi[base + (size_t)n * CC + c0 + tx] = h;
        g_Xt_lo[base + (size_t)n * CC + c0 + tx] =
            __float2bfloat16(v - __bfloat162float(h));
    }
}

// ---------------------------------------------------------------------------
// k_Zt: Zt[n][d] = sum_c Xt[n][c] * A[d][c]   (3-term bf16 split, mma.sync)
// ---------------------------------------------------------------------------
__global__ __launch_bounds__(256, 1) void k_Zt() {
    extern __shared__ char smem[];
    const uint32_t sb = smem_u32(smem);
    const int tid = threadIdx.x;
    const int wid = tid >> 5, lane = tid & 31;
    const int g = lane >> 2;
    const int n0 = blockIdx.x << 7;
    const int d0 = blockIdx.y << 7;
    const int b = blockIdx.z;
    const size_t bbase = (size_t)b * NN * CC;
    const char* Xsrc[2] = {(const char*)(g_Xt_hi + bbase), (const char*)(g_Xt_lo + bbase)};
    const char* Asrc[2] = {(const char*)g_Ah, (const char*)g_Al};

    const int aRow = wid * 16 + (lane & 15);
    const uint32_t aOff = (uint32_t)(aRow * 128);
    const uint32_t aSwz = (uint32_t)((aRow * 16) & 0x70);
    const int aColX = (lane >> 4) << 4;
    const int bRowOff = (lane & 7) + ((lane >> 4) & 1) * 8;
    const int bColX = ((lane >> 3) & 1) << 4;

    float acc[16][4];
#pragma unroll
    for (int i = 0; i < 16; i++)
#pragma unroll
        for (int j = 0; j < 4; j++) acc[i][j] = 0.f;

#pragma unroll
    for (int t = 0; t < 16; t++) {
        int o = tid + t * 256;
        int role = o >> 10, r = (o >> 3) & 127, j = o & 7;
        const char* src = (role < 2)
            ? Xsrc[role] + ((size_t)(n0 + r) * CC) * 2 + j * 16
            : Asrc[role - 2] + ((size_t)(d0 + r) * CC) * 2 + j * 16;
        uint32_t dst = sb + (uint32_t)role * 16384u + SWZ((uint32_t)(r * 128 + j * 16));
        CP16(dst, src);
    }
    CP_COMMIT();

#pragma unroll 1
    for (int cc = 0; cc < 4; cc++) {
        const int buf = cc & 1;
        CP_WAIT0();
        __syncthreads();
        if (cc < 3) {
            const int cn = cc + 1, bn = buf ^ 1;
#pragma unroll
            for (int t = 0; t < 16; t++) {
                int o = tid + t * 256;
                int role = o >> 10, r = (o >> 3) & 127, j = o & 7;
                const char* src = (role < 2)
                    ? Xsrc[role] + ((size_t)(n0 + r) * CC + cn * 64) * 2 + j * 16
                    : Asrc[role - 2] + ((size_t)(d0 + r) * CC + cn * 64) * 2 + j * 16;
                uint32_t dst = sb + (uint32_t)(bn * 4 + role) * 16384u +
                               SWZ((uint32_t)(r * 128 + j * 16));
                CP16(dst, src);
            }
        }
        CP_COMMIT();

        const uint32_t xh = sb + (uint32_t)(buf * 4 + 0) * 16384u;
        const uint32_t xl = xh + 16384u;
        const uint32_t ah = sb + (uint32_t)(buf * 4 + 2) * 16384u;
        const uint32_t al = ah + 16384u;
#pragma unroll
        for (int ks = 0; ks < 4; ks++) {
            const int cb = ks * 32;
            uint32_t Ah[4], Al[4];
            uint32_t aoff = aOff + (uint32_t)((cb + aColX) ^ aSwz);
            ldsm4(Ah, xh + aoff);
            ldsm4(Al, xl + aoff);
#pragma unroll
            for (int j2 = 0; j2 < 8; j2++) {
                uint32_t Bh[4], Bl[4];
                int brow = j2 * 16 + bRowOff;
                uint32_t boff = (uint32_t)(brow * 128) +
                                (uint32_t)((cb + bColX) ^ ((brow * 16) & 0x70));
                ldsm4(Bh, ah + boff);
                ldsm4(Bl, al + boff);
                mma16816(acc[j2 * 2],     Ah, Bh);
                mma16816(acc[j2 * 2 + 1], Ah, Bh + 2);
                mma16816(acc[j2 * 2],     Ah, Bl);
                mma16816(acc[j2 * 2 + 1], Ah, Bl + 2);
                mma16816(acc[j2 * 2],     Al, Bh);
                mma16816(acc[j2 * 2 + 1], Al, Bh + 2);
            }
        }
    }

    char* Zh = (char*)(g_Zt_hi + bbase);
    char* Zl = (char*)(g_Zt_lo + bbase);
#pragma unroll
    for (int h = 0; h < 2; h++) {
        int n = n0 + wid * 16 + h * 8 + g;
#pragma unroll
        for (int bt = 0; bt < 16; bt++) {
            float v0 = acc[bt][2 * h], v1 = acc[bt][2 * h + 1];
            __nv_bfloat16 h0 = __float2bfloat16(v0);
            __nv_bfloat16 h1 = __float2bfloat16(v1);
            __nv_bfloat16 l0 = __float2bfloat16(v0 - __bfloat162float(h0));
            __nv_bfloat16 l1 = __float2bfloat16(v1 - __bfloat162float(h1));
            size_t off = ((size_t)n * CC + d0 + bt * 8 + 2 * (lane & 3)) * 2;
            *(uint32_t*)(Zh + off) = pack_bf16x2(h0, h1);
            *(uint32_t*)(Zl + off) = pack_bf16x2(l0, l1);
        }
    }
}

// ---------------------------------------------------------------------------
// k_part: partial softmax over one m-quarter (8 m-tiles of 128 cols).
// grid = B*32*4 (bx -> b, nt, mq), 512 threads (16 warps, 4x4, 32x32 tiles).
// Z persistent in smem (128KB), X triple-buffered K=64 chunks (3x32KB),
// cp.async.wait_group 1 so every load has 2 chunk-times to land.
// R9 = R6 + term-major MMA issue order (acc reuse distance 8, was 2).
// ---------------------------------------------------------------------------
#define SM_ZS 0u
#define SM_XS 131072u
#define SM_TOTAL (131072 + 3 * 32768)

__global__ __launch_bounds__(512, 1) void k_part() {
    extern __shared__ char smem[];
    const uint32_t sb = smem_u32(smem);
    const int tid = threadIdx.x;
    const int wid = tid >> 5, lane = tid & 31;
    const int wr = wid >> 2, wc = wid & 3;
    const int g = lane >> 2;
    const int bx = blockIdx.x;
    const int b = bx >> 7;
    const int nt = (bx >> 2) & 31;
    const int mq = bx & 3;
    const int n0 = nt << 7;
    const size_t bbase = (size_t)b * NN * CC;
    const char* Zsrc[2] = {(const char*)(g_Zt_hi + bbase), (const char*)(g_Zt_lo + bbase)};
    const char* Xsrc[2] = {(const char*)(g_Xt_hi + bbase), (const char*)(g_Xt_lo + bbase)};

    const int aColX = (lane >> 4) << 4;
    const int bRowOff = (lane & 7) + ((lane >> 4) & 1) * 8;
    const int bColX = ((lane >> 3) & 1) << 4;

    // prologue: group0 = Z (8 tiles) + X chunk0 ; group1 = X chunk1
#pragma unroll
    for (int t = 0; t < 16; t++) {
        int o = tid + t * 512;
        int ch = o >> 11, hs = (o >> 10) & 1, r = (o >> 3) & 127, j = o & 7;
        const char* src = Zsrc[hs] + ((size_t)(n0 + r) * CC + ch * 64) * 2 + j * 16;
        uint32_t dst = sb + SM_ZS + (uint32_t)(ch * 2 + hs) * 16384u +
                       SWZ((uint32_t)(r * 128 + j * 16));
        CP16(dst, src);
    }
    {
        const int m00 = (mq * 8) << 7;
#pragma unroll
        for (int t = 0; t < 4; t++) {
            int o = tid + t * 512;
            int hs = o >> 10, r = (o >> 3) & 127, j = o & 7;
            const char* src = Xsrc[hs] + ((size_t)(m00 + r) * CC) * 2 + j * 16;
            uint32_t dst = sb + SM_XS + (uint32_t)hs * 16384u +
                           SWZ((uint32_t)(r * 128 + j * 16));
            CP16(dst, src);
        }
        CP_COMMIT();   // group 0
#pragma unroll
        for (int t = 0; t < 4; t++) {
            int o = tid + t * 512;
            int hs = o >> 10, r = (o >> 3) & 127, j = o & 7;
            const char* src = Xsrc[hs] + ((size_t)(m00 + r) * CC + 64) * 2 + j * 16;
            uint32_t dst = sb + SM_XS + 32768u + (uint32_t)hs * 16384u +
                           SWZ((uint32_t)(r * 128 + j * 16));
            CP16(dst, src);
        }
        CP_COMMIT();   // group 1
    }

    float acc[2][4][4];
#pragma unroll
    for (int i = 0; i < 2; i++)
#pragma unroll
        for (int j = 0; j < 4; j++)
#pragma unroll
            for (int k = 0; k < 4; k++) acc[i][j][k] = 0.f;
    float mrun[2][2], rsum[2][2];
#pragma unroll
    for (int i = 0; i < 2; i++)
#pragma unroll
        for (int j = 0; j < 2; j++) { mrun[i][j] = -3.0e38f; rsum[i][j] = 0.f; }

    int buf = 0, bufp = 2;   // buf = G%3, bufp = (G+2)%3

#pragma unroll 1
    for (int G = 0; G < 32; G++) {
        const int cc = G & 3, mtl = G >> 2;
        CP_WAIT1();          // chunk G (issued 2 iters ago) has landed
        __syncthreads();

        // prefetch chunk G+2 into buf (G+2)%3
        if (G + 2 < 32) {
            const int Gn = G + 2;
            const int ccn = Gn & 3, m0n = (mq * 8 + (Gn >> 2)) << 7;
#pragma unroll
            for (int t = 0; t < 4; t++) {
                int o = tid + t * 512;
                int hs = o >> 10, r = (o >> 3) & 127, j = o & 7;
                const char* src = Xsrc[hs] + ((size_t)(m0n + r) * CC + ccn * 64) * 2 + j * 16;
                uint32_t dst = sb + SM_XS + (uint32_t)bufp * 32768u +
                               (uint32_t)hs * 16384u + SWZ((uint32_t)(r * 128 + j * 16));
                CP16(dst, src);
            }
        }
        CP_COMMIT();

        const uint32_t zh = sb + SM_ZS + (uint32_t)(cc * 2) * 16384u;
        const uint32_t zl = zh + 16384u;
        const uint32_t xh = sb + SM_XS + (uint32_t)buf * 32768u;
        const uint32_t xl = xh + 16384u;
#pragma unroll
        for (int ks = 0; ks < 4; ks++) {
            const int cb = ks * 32;
            uint32_t Ah[2][4], Al[2][4], Bh[2][4], Bl[2][4];
#pragma unroll
            for (int rb = 0; rb < 2; rb++) {
                int row = wr * 32 + rb * 16 + (lane & 15);
                uint32_t off = (uint32_t)(row * 128) +
                               (uint32_t)((cb + aColX) ^ ((row * 16) & 0x70));
                ldsm4(Ah[rb], zh + off);
                ldsm4(Al[rb], zl + off);
            }
#pragma unroll
            for (int cs = 0; cs < 2; cs++) {
                int row = wc * 32 + cs * 16 + bRowOff;
                uint32_t off = (uint32_t)(row * 128) +
                               (uint32_t)((cb + bColX) ^ ((row * 16) & 0x70));
                ldsm4(Bh[cs], xh + off);
                ldsm4(Bl[cs], xl + off);
            }
            // term-major issue order: 8 distinct accumulators per term,
            // acc reuse distance = 8 (was 2) -> hides HMMA result latency.
#pragma unroll
            for (int rb = 0; rb < 2; rb++)
#pragma unroll
                for (int cs = 0; cs < 2; cs++) {
                    mma16816(acc[rb][cs * 2],     Ah[rb], Bh[cs]);
                    mma16816(acc[rb][cs * 2 + 1], Ah[rb], Bh[cs] + 2);
                }
#pragma unroll
            for (int rb = 0; rb < 2; rb++)
#pragma unroll
                for (int cs = 0; cs < 2; cs++) {
                    mma16816(acc[rb][cs * 2],     Ah[rb], Bl[cs]);
                    mma16816(acc[rb][cs * 2 + 1], Ah[rb], Bl[cs] + 2);
                }
#pragma unroll
            for (int rb = 0; rb < 2; rb++)
#pragma unroll
                for (int cs = 0; cs < 2; cs++) {
                    mma16816(acc[rb][cs * 2],     Al[rb], Bh[cs]);
                    mma16816(acc[rb][cs * 2 + 1], Al[rb], Bh[cs] + 2);
                }
        }

        // ---- tile boundary: online softmax ----
        if (cc == 3) {
            // all warps must finish ldsm of buf before scratch scrawl
            __syncthreads();
            float* pmax = (float*)(smem + SM_XS + (uint32_t)buf * 32768u);
            float* psum = pmax + 512;

#pragma unroll
            for (int rb = 0; rb < 2; rb++)
#pragma unroll
                for (int rh = 0; rh < 2; rh++) {
                    float tm = -3.0e38f;
#pragma unroll
                    for (int j = 0; j < 4; j++)
                        tm = fmaxf(tm, fmaxf(acc[rb][j][2 * rh], acc[rb][j][2 * rh + 1]));
                    tm = fmaxf(tm, __shfl_xor_sync(0xffffffffu, tm, 1));
                    tm = fmaxf(tm, __shfl_xor_sync(0xffffffffu, tm, 2));
                    float ps = 0.f;
#pragma unroll
                    for (int j = 0; j < 4; j++) {
                        ps += fexp2(acc[rb][j][2 * rh] - tm);
                        ps += fexp2(acc[rb][j][2 * rh + 1] - tm);
                    }
                    ps += __shfl_xor_sync(0xffffffffu, ps, 1);
                    ps += __shfl_xor_sync(0xffffffffu, ps, 2);
                    if ((lane & 3) == 0) {
                        int rl = wr * 32 + rb * 16 + rh * 8 + g;
                        pmax[wc * 128 + rl] = tm;
                        psum[wc * 128 + rl] = ps;
                    }
                }
            // diagonal capture (raw log2-logit) -> gmem
            if (mq == (nt >> 3) && mtl == (nt & 7) && wr == wc) {
#pragma unroll
                for (int rb = 0; rb < 2; rb++)
#pragma unroll
                    for (int rh = 0; rh < 2; rh++) {
                        int cl = rb * 16 + rh * 8 + g;
                        if ((lane & 3) == ((cl & 7) >> 1))
                            g_dlog[(size_t)(b * 32 + nt) * 128 + wr * 32 + cl] =
                                acc[rb][rb * 2 + rh][2 * rh + (cl & 1)];
                    }
            }
            __syncthreads();
            // replicated combine
#pragma unroll
            for (int rb = 0; rb < 2; rb++)
#pragma unroll
                for (int rh = 0; rh < 2; rh++) {
                    int rl = wr * 32 + rb * 16 + rh * 8 + g;
                    float mn = mrun[rb][rh];
#pragma unroll
                    for (int j = 0; j < 4; j++) mn = fmaxf(mn, pmax[j * 128 + rl]);
                    float rs = rsum[rb][rh] * fexp2(mrun[rb][rh] - mn);
#pragma unroll
                    for (int j = 0; j < 4; j++)
                        rs += fexp2(pmax[j * 128 + rl] - mn) * psum[j * 128 + rl];
                    mrun[rb][rh] = mn;
                    rsum[rb][rh] = rs;
                }
#pragma unroll
            for (int i = 0; i < 2; i++)
#pragma unroll
                for (int j = 0; j < 4; j++)
#pragma unroll
                    for (int k = 0; k < 4; k++) acc[i][j][k] = 0.f;
        }

        buf = (buf == 2) ? 0 : buf + 1;
        bufp = (bufp == 2) ? 0 : bufp + 1;
    }

    // write partial state
    if (wc == 0 && (lane & 3) == 0) {
#pragma unroll
        for (int rb = 0; rb < 2; rb++)
#pragma unroll
            for (int rh = 0; rh < 2; rh++) {
                int rl = wr * 32 + rb * 16 + rh * 8 + g;
                g_pm[(size_t)bx * 128 + rl] = mrun[rb][rh];
                g_ps[(size_t)bx * 128 + rl] = rsum[rb][rh];
            }
    }
}

// ---------------------------------------------------------------------------
// k_final: combine 4 partials -> diag; out[b][c][n0..] = X * diag
// ---------------------------------------------------------------------------
__global__ __launch_bounds__(512) void k_final(const float* __restrict__ X,
                                               float* __restrict__ out) {
    __shared__ float sdiag[128];
    const int bx = blockIdx.x;
    const int b = bx >> 5, nt = bx & 31;
    const int n0 = nt << 7;
    const int tid = threadIdx.x;

    if (tid < 128) {
        float pm[4];
        float M = -3.0e38f;
#pragma unroll
        for (int q = 0; q < 4; q++) {
            pm[q] = g_pm[((size_t)bx * 4 + q) * 128 + tid];
            M = fmaxf(M, pm[q]);
        }
        float S = 0.f;
#pragma unroll
        for (int q = 0; q < 4; q++)
            S += g_ps[((size_t)bx * 4 + q) * 128 + tid] * fexp2(pm[q] - M);
        sdiag[tid] = fexp2(g_dlog[(size_t)bx * 128 + tid] - M) / S *
                     (1.0f / (1.0f + 1e-8f));
    }
    __syncthreads();

    const float* Xb = X + (size_t)b * CC * NN;
    float* Ob = out + (size_t)b * CC * NN;
#pragma unroll 4
    for (int t = 0; t < 16; t++) {
        int f = tid + t * 512;
        int row = f >> 5;
        int c4 = (f & 31) << 2;
        float4 v = *(const float4*)&Xb[(size_t)row * NN + n0 + c4];
        float4 dv = *(const float4*)&sdiag[c4];
        v.x *= dv.x; v.y *= dv.y; v.z *= dv.z; v.w *= dv.w;
        *(float4*)&Ob[(size_t)row * NN + n0 + c4] = v;
    }
}

// ---------------------------------------------------------------------------
extern "C" void kernel_launch(void* const* d_in, const int* in_sizes, int n_in,
                              void* d_out, int out_size) {
    const float* X  = (const float*)d_in[0];
    const float* Wq = (const float*)d_in[1];
    const float* Wk = (const float*)d_in[2];
    float* out = (float*)d_out;

    cudaFuncSetAttribute(k_Zt, cudaFuncAttributeMaxDynamicSharedMemorySize, 131072);
    cudaFuncSetAttribute(k_part, cudaFuncAttributeMaxDynamicSharedMemorySize, SM_TOTAL);

    k_prepA<<<dim3(8, 32), dim3(32, 8)>>>(Wq, Wk);
    k_prep<<<dim3(NN / 32, CC / 32, BB), dim3(32, 8)>>>(X);
    k_Zt<<<dim3(32, 2, BB), 256, 131072>>>();
    k_part<<<BB * 32 * 4, 512, SM_TOTAL>>>();
    k_final<<<BB * 32, 512>>>(X, out);
}

// round 11
// speedup vs baseline: 1.8592x; 1.0033x over previous
#include <cuda_runtime.h>
#include <cuda_bf16.h>
#include <cstdint>

#define CC 256
#define NN 4096
#define BB 8

// ---------------- device globals (no runtime allocs allowed) ----------------
static __device__ __nv_bfloat16 g_Ah[CC * CC];      // A hi  [d][c]
static __device__ __nv_bfloat16 g_Al[CC * CC];      // A lo
static __device__ __nv_bfloat16 g_Xt_hi[(size_t)BB * NN * CC];  // X^T hi [b][n][c]
static __device__ __nv_bfloat16 g_Xt_lo[(size_t)BB * NN * CC];
static __device__ __nv_bfloat16 g_Zt_hi[(size_t)BB * NN * CC];  // Z^T hi [b][n][d]
static __device__ __nv_bfloat16 g_Zt_lo[(size_t)BB * NN * CC];
// split-softmax partials: [b*32+nt][mq][row]
static __device__ float g_pm[(size_t)BB * 32 * 4 * 128];
static __device__ float g_ps[(size_t)BB * 32 * 4 * 128];
static __device__ float g_dlog[(size_t)BB * 32 * 128];

// ---------------- helpers ----------------
__device__ __forceinline__ float fexp2(float x) {
    float y;
    asm("ex2.approx.ftz.f32 %0, %1;" : "=f"(y) : "f"(x));
    return y;
}
__device__ __forceinline__ uint32_t smem_u32(const void* p) {
    uint32_t a;
    asm("{ .reg .u64 t; cvta.to.shared.u64 t, %1; cvt.u32.u64 %0, t; }" : "=r"(a) : "l"(p));
    return a;
}
#define SWZ(o) ((o) ^ (((o) >> 3) & 0x70))

#define CP16(dst, src) \
    asm volatile("cp.async.cg.shared.global [%0], [%1], 16;" :: "r"(dst), "l"(src) : "memory")
#define CP_COMMIT() asm volatile("cp.async.commit_group;" ::: "memory")
#define CP_WAIT0()  asm volatile("cp.async.wait_group 0;" ::: "memory")

// mbarrier ops
#define MBAR_INIT(a, n) \
    asm volatile("mbarrier.init.shared.b64 [%0], %1;" :: "r"(a), "r"(n) : "memory")
#define MBAR_ARRIVE(a) \
    asm volatile("mbarrier.arrive.shared.b64 _, [%0];" :: "r"(a) : "memory")
#define CP_MBAR_ARRIVE(a) \
    asm volatile("cp.async.mbarrier.arrive.noinc.shared.b64 [%0];" :: "r"(a) : "memory")
#define MBAR_WAIT(a, ph) do {                                                         \
    uint32_t _m = (a), _p = (ph), _d;                                                 \
    asm volatile("{\n\t.reg .pred p;\n\t"                                             \
        "mbarrier.try_wait.parity.acquire.cta.shared::cta.b64 p, [%1], %2;\n\t"       \
        "selp.b32 %0, 1, 0, p;\n\t}" : "=r"(_d) : "r"(_m), "r"(_p) : "memory");       \
    if (!_d) {                                                                        \
        asm volatile("{\n\t.reg .pred P1;\n\tWL_%=:\n\t"                              \
            "mbarrier.try_wait.parity.acquire.cta.shared::cta.b64 P1, [%0], %1, 0x989680;\n\t" \
            "@P1 bra.uni WD_%=;\n\tbra.uni WL_%=;\n\tWD_%=:\n\t}"                     \
            :: "r"(_m), "r"(_p) : "memory");                                          \
    }                                                                                 \
} while (0)

__device__ __forceinline__ void ldsm4(uint32_t* r, uint32_t a) {
    asm volatile("ldmatrix.sync.aligned.m8n8.x4.shared.b16 {%0,%1,%2,%3}, [%4];"
        : "=r"(r[0]), "=r"(r[1]), "=r"(r[2]), "=r"(r[3]) : "r"(a));
}
__device__ __forceinline__ void mma16816(float* d, const uint32_t* a, const uint32_t* b) {
    asm volatile("mma.sync.aligned.m16n8k16.row.col.f32.bf16.bf16.f32 "
        "{%0,%1,%2,%3}, {%4,%5,%6,%7}, {%8,%9}, {%0,%1,%2,%3};"
        : "+f"(d[0]), "+f"(d[1]), "+f"(d[2]), "+f"(d[3])
        : "r"(a[0]), "r"(a[1]), "r"(a[2]), "r"(a[3]), "r"(b[0]), "r"(b[1]));
}
__device__ __forceinline__ uint32_t pack_bf16x2(__nv_bfloat16 a, __nv_bfloat16 b) {
    return (uint32_t)__bfloat16_as_ushort(a) | ((uint32_t)__bfloat16_as_ushort(b) << 16);
}

// ---------------------------------------------------------------------------
// A[d][c] = log2e * sum_e Wq[e][c] * Wk[e][d], stored as bf16 hi/lo
// ---------------------------------------------------------------------------
__global__ void k_prepA(const float* __restrict__ Wq, const float* __restrict__ Wk) {
    const float LOG2E = 1.4426950408889634f;
    int c = blockIdx.x * 32 + threadIdx.x;
    int d = blockIdx.y * 8 + threadIdx.y;
    float s0 = 0.f, s1 = 0.f;
#pragma unroll 8
    for (int e = 0; e < CC; e += 2) {
        s0 = fmaf(Wq[e * CC + c], Wk[e * CC + d], s0);
        s1 = fmaf(Wq[(e + 1) * CC + c], Wk[(e + 1) * CC + d], s1);
    }
    float v = (s0 + s1) * LOG2E;
    __nv_bfloat16 h = __float2bfloat16(v);
    g_Ah[d * CC + c] = h;
    g_Al[d * CC + c] = __float2bfloat16(v - __bfloat162float(h));
}

// ---------------------------------------------------------------------------
// Transpose + bf16 hi/lo split: X[b][c][n] -> Xt_hi/lo[b][n][c]
// ---------------------------------------------------------------------------
__global__ __launch_bounds__(256) void k_prep(const float* __restrict__ X) {
    __shared__ float s[32][33];
    const int b = blockIdx.z, c0 = blockIdx.y * 32, n0 = blockIdx.x * 32;
    const int tx = threadIdx.x, ty = threadIdx.y;
    const float* Xb = X + (size_t)b * CC * NN;
#pragma unroll
    for (int i = 0; i < 4; i++)
        s[ty + 8 * i][tx] = Xb[(size_t)(c0 + ty + 8 * i) * NN + n0 + tx];
    __syncthreads();
    const size_t base = (size_t)b * NN * CC;
#pragma unroll
    for (int i = 0; i < 4; i++) {
        int n = n0 + ty + 8 * i;
        float v = s[tx][ty + 8 * i];
        __nv_bfloat16 h = __float2bfloat16(v);
        g_Xt_hi[base + (size_t)n * CC + c0 + tx] = h;
        g_Xt_lo[base + (size_t)n * CC + c0 + tx] =
            __float2bfloat16(v - __bfloat162float(h));
    }
}

// ---------------------------------------------------------------------------
// k_Zt: Zt[n][d] = sum_c Xt[n][c] * A[d][c]   (3-term bf16 split, mma.sync)
// ---------------------------------------------------------------------------
__global__ __launch_bounds__(256, 1) void k_Zt() {
    extern __shared__ char smem[];
    const uint32_t sb = smem_u32(smem);
    const int tid = threadIdx.x;
    const int wid = tid >> 5, lane = tid & 31;
    const int g = lane >> 2;
    const int n0 = blockIdx.x << 7;
    const int d0 = blockIdx.y << 7;
    const int b = blockIdx.z;
    const size_t bbase = (size_t)b * NN * CC;
    const char* Xsrc[2] = {(const char*)(g_Xt_hi + bbase), (const char*)(g_Xt_lo + bbase)};
    const char* Asrc[2] = {(const char*)g_Ah, (const char*)g_Al};

    const int aRow = wid * 16 + (lane & 15);
    const uint32_t aOff = (uint32_t)(aRow * 128);
    const uint32_t aSwz = (uint32_t)((aRow * 16) & 0x70);
    const int aColX = (lane >> 4) << 4;
    const int bRowOff = (lane & 7) + ((lane >> 4) & 1) * 8;
    const int bColX = ((lane >> 3) & 1) << 4;

    float acc[16][4];
#pragma unroll
    for (int i = 0; i < 16; i++)
#pragma unroll
        for (int j = 0; j < 4; j++) acc[i][j] = 0.f;

#pragma unroll
    for (int t = 0; t < 16; t++) {
        int o = tid + t * 256;
        int role = o >> 10, r = (o >> 3) & 127, j = o & 7;
        const char* src = (role < 2)
            ? Xsrc[role] + ((size_t)(n0 + r) * CC) * 2 + j * 16
            : Asrc[role - 2] + ((size_t)(d0 + r) * CC) * 2 + j * 16;
        uint32_t dst = sb + (uint32_t)role * 16384u + SWZ((uint32_t)(r * 128 + j * 16));
        CP16(dst, src);
    }
    CP_COMMIT();

#pragma unroll 1
    for (int cc = 0; cc < 4; cc++) {
        const int buf = cc & 1;
        CP_WAIT0();
        __syncthreads();
        if (cc < 3) {
            const int cn = cc + 1, bn = buf ^ 1;
#pragma unroll
            for (int t = 0; t < 16; t++) {
                int o = tid + t * 256;
                int role = o >> 10, r = (o >> 3) & 127, j = o & 7;
                const char* src = (role < 2)
                    ? Xsrc[role] + ((size_t)(n0 + r) * CC + cn * 64) * 2 + j * 16
                    : Asrc[role - 2] + ((size_t)(d0 + r) * CC + cn * 64) * 2 + j * 16;
                uint32_t dst = sb + (uint32_t)(bn * 4 + role) * 16384u +
                               SWZ((uint32_t)(r * 128 + j * 16));
                CP16(dst, src);
            }
        }
        CP_COMMIT();

        const uint32_t xh = sb + (uint32_t)(buf * 4 + 0) * 16384u;
        const uint32_t xl = xh + 16384u;
        const uint32_t ah = sb + (uint32_t)(buf * 4 + 2) * 16384u;
        const uint32_t al = ah + 16384u;
#pragma unroll
        for (int ks = 0; ks < 4; ks++) {
            const int cb = ks * 32;
            uint32_t Ah[4], Al[4];
            uint32_t aoff = aOff + (uint32_t)((cb + aColX) ^ aSwz);
            ldsm4(Ah, xh + aoff);
            ldsm4(Al, xl + aoff);
#pragma unroll
            for (int j2 = 0; j2 < 8; j2++) {
                uint32_t Bh[4], Bl[4];
                int brow = j2 * 16 + bRowOff;
                uint32_t boff = (uint32_t)(brow * 128) +
                                (uint32_t)((cb + bColX) ^ ((brow * 16) & 0x70));
                ldsm4(Bh, ah + boff);
                ldsm4(Bl, al + boff);
                mma16816(acc[j2 * 2],     Ah, Bh);
                mma16816(acc[j2 * 2 + 1], Ah, Bh + 2);
                mma16816(acc[j2 * 2],     Ah, Bl);
                mma16816(acc[j2 * 2 + 1], Ah, Bl + 2);
                mma16816(acc[j2 * 2],     Al, Bh);
                mma16816(acc[j2 * 2 + 1], Al, Bh + 2);
            }
        }
    }

    char* Zh = (char*)(g_Zt_hi + bbase);
    char* Zl = (char*)(g_Zt_lo + bbase);
#pragma unroll
    for (int h = 0; h < 2; h++) {
        int n = n0 + wid * 16 + h * 8 + g;
#pragma unroll
        for (int bt = 0; bt < 16; bt++) {
            float v0 = acc[bt][2 * h], v1 = acc[bt][2 * h + 1];
            __nv_bfloat16 h0 = __float2bfloat16(v0);
            __nv_bfloat16 h1 = __float2bfloat16(v1);
            __nv_bfloat16 l0 = __float2bfloat16(v0 - __bfloat162float(h0));
            __nv_bfloat16 l1 = __float2bfloat16(v1 - __bfloat162float(h1));
            size_t off = ((size_t)n * CC + d0 + bt * 8 + 2 * (lane & 3)) * 2;
            *(uint32_t*)(Zh + off) = pack_bf16x2(h0, h1);
            *(uint32_t*)(Zl + off) = pack_bf16x2(l0, l1);
        }
    }
}

// ---------------------------------------------------------------------------
// k_part: partial softmax over one m-quarter. grid B*32*4, 512 threads,
// 16 warps 4x4, warp tile 32x32. Z persistent (128KB), X triple-buffered.
// mbarrier producer/consumer (full[3]/free[3]) replaces the per-iteration
// block barrier so LDSM of one warp overlaps MMA of another.
// ---------------------------------------------------------------------------
#define SM_ZS 0u
#define SM_XS 131072u
#define SM_MBAR 229376u
#define SM_TOTAL (229376 + 64)

__global__ __launch_bounds__(512, 1) void k_part() {
    extern __shared__ char smem[];
    const uint32_t sb = smem_u32(smem);
    const int tid = threadIdx.x;
    const int wid = tid >> 5, lane = tid & 31;
    const int wr = wid >> 2, wc = wid & 3;
    const int g = lane >> 2;
    const int bx = blockIdx.x;
    const int b = bx >> 7;
    const int nt = (bx >> 2) & 31;
    const int mq = bx & 3;
    const int n0 = nt << 7;
    const size_t bbase = (size_t)b * NN * CC;
    const char* Zsrc[2] = {(const char*)(g_Zt_hi + bbase), (const char*)(g_Zt_lo + bbase)};
    const char* Xsrc[2] = {(const char*)(g_Xt_hi + bbase), (const char*)(g_Xt_lo + bbase)};

    const uint32_t mb_full = sb + SM_MBAR;        // full[k] = +8k
    const uint32_t mb_free = sb + SM_MBAR + 24;   // free[k] = +24+8k

    const int aColX = (lane >> 4) << 4;
    const int bRowOff = (lane & 7) + ((lane >> 4) & 1) * 8;
    const int bColX = ((lane >> 3) & 1) << 4;

    if (tid == 0) {
#pragma unroll
        for (int k = 0; k < 3; k++) {
            MBAR_INIT(mb_full + k * 8, 512);
            MBAR_INIT(mb_free + k * 8, 512);
        }
    }
    __syncthreads();

    // prologue pre-arrivals: free[0..2] phase 0
    MBAR_ARRIVE(mb_free + 0);
    MBAR_ARRIVE(mb_free + 8);
    MBAR_ARRIVE(mb_free + 16);

    // Z (8 tiles, SW128)
#pragma unroll
    for (int t = 0; t < 16; t++) {
        int o = tid + t * 512;
        int ch = o >> 11, hs = (o >> 10) & 1, r = (o >> 3) & 127, j = o & 7;
        const char* src = Zsrc[hs] + ((size_t)(n0 + r) * CC + ch * 64) * 2 + j * 16;
        uint32_t dst = sb + SM_ZS + (uint32_t)(ch * 2 + hs) * 16384u +
                       SWZ((uint32_t)(r * 128 + j * 16));
        CP16(dst, src);
    }
    // chunk 0 -> buffer 0 (its arrive also covers the Z copies above)
    {
        const int m00 = (mq * 8) << 7;
#pragma unroll
        for (int t = 0; t < 4; t++) {
            int o = tid + t * 512;
            int hs = o >> 10, r = (o >> 3) & 127, j = o & 7;
            const char* src = Xsrc[hs] + ((size_t)(m00 + r) * CC) * 2 + j * 16;
            uint32_t dst = sb + SM_XS + (uint32_t)hs * 16384u +
                           SWZ((uint32_t)(r * 128 + j * 16));
            CP16(dst, src);
        }
        CP_MBAR_ARRIVE(mb_full + 0);
        // chunk 1 -> buffer 1
#pragma unroll
        for (int t = 0; t < 4; t++) {
            int o = tid + t * 512;
            int hs = o >> 10, r = (o >> 3) & 127, j = o & 7;
            const char* src = Xsrc[hs] + ((size_t)(m00 + r) * CC + 64) * 2 + j * 16;
            uint32_t dst = sb + SM_XS + 32768u + (uint32_t)hs * 16384u +
                           SWZ((uint32_t)(r * 128 + j * 16));
            CP16(dst, src);
        }
        CP_MBAR_ARRIVE(mb_full + 8);
    }

    float acc[2][4][4];
#pragma unroll
    for (int i = 0; i < 2; i++)
#pragma unroll
        for (int j = 0; j < 4; j++)
#pragma unroll
            for (int k = 0; k < 4; k++) acc[i][j][k] = 0.f;
    float mrun[2][2], rsum[2][2];
#pragma unroll
    for (int i = 0; i < 2; i++)
#pragma unroll
        for (int j = 0; j < 2; j++) { mrun[i][j] = -3.0e38f; rsum[i][j] = 0.f; }

#pragma unroll 1
    for (int G = 0; G < 32; G++) {
        const int cc = G & 3, mtl = G >> 2;
        const int buf = G % 3;

        // ---- producer: chunk G+2 into buffer (G+2)%3 ----
        const int Gn = G + 2;
        if (Gn < 32) {
            const int k2 = Gn % 3;
            MBAR_WAIT(mb_free + k2 * 8, (Gn / 3) & 1);
            const int ccn = Gn & 3, m0n = (mq * 8 + (Gn >> 2)) << 7;
#pragma unroll
            for (int t = 0; t < 4; t++) {
                int o = tid + t * 512;
                int hs = o >> 10, r = (o >> 3) & 127, j = o & 7;
                const char* src = Xsrc[hs] + ((size_t)(m0n + r) * CC + ccn * 64) * 2 + j * 16;
                uint32_t dst = sb + SM_XS + (uint32_t)k2 * 32768u +
                               (uint32_t)hs * 16384u + SWZ((uint32_t)(r * 128 + j * 16));
                CP16(dst, src);
            }
            CP_MBAR_ARRIVE(mb_full + k2 * 8);
        }

        // ---- consumer: wait chunk G, then ldsm/MMA ----
        MBAR_WAIT(mb_full + buf * 8, (G / 3) & 1);

        const uint32_t zh = sb + SM_ZS + (uint32_t)(cc * 2) * 16384u;
        const uint32_t zl = zh + 16384u;
        const uint32_t xh = sb + SM_XS + (uint32_t)buf * 32768u;
        const uint32_t xl = xh + 16384u;
#pragma unroll
        for (int ks = 0; ks < 4; ks++) {
            const int cb = ks * 32;
            uint32_t Ah[2][4], Al[2][4], Bh[2][4], Bl[2][4];
#pragma unroll
            for (int rb = 0; rb < 2; rb++) {
                int row = wr * 32 + rb * 16 + (lane & 15);
                uint32_t off = (uint32_t)(row * 128) +
                               (uint32_t)((cb + aColX) ^ ((row * 16) & 0x70));
                ldsm4(Ah[rb], zh + off);
                ldsm4(Al[rb], zl + off);
            }
#pragma unroll
            for (int cs = 0; cs < 2; cs++) {
                int row = wc * 32 + cs * 16 + bRowOff;
                uint32_t off = (uint32_t)(row * 128) +
                               (uint32_t)((cb + bColX) ^ ((row * 16) & 0x70));
                ldsm4(Bh[cs], xh + off);
                ldsm4(Bl[cs], xl + off);
            }
#pragma unroll
            for (int rb = 0; rb < 2; rb++)
#pragma unroll
                for (int cs = 0; cs < 2; cs++) {
                    mma16816(acc[rb][cs * 2],     Ah[rb], Bh[cs]);
                    mma16816(acc[rb][cs * 2 + 1], Ah[rb], Bh[cs] + 2);
                }
#pragma unroll
            for (int rb = 0; rb < 2; rb++)
#pragma unroll
                for (int cs = 0; cs < 2; cs++) {
                    mma16816(acc[rb][cs * 2],     Ah[rb], Bl[cs]);
                    mma16816(acc[rb][cs * 2 + 1], Ah[rb], Bl[cs] + 2);
                }
#pragma unroll
            for (int rb = 0; rb < 2; rb++)
#pragma unroll
                for (int cs = 0; cs < 2; cs++) {
                    mma16816(acc[rb][cs * 2],     Al[rb], Bh[cs]);
                    mma16816(acc[rb][cs * 2 + 1], Al[rb], Bh[cs] + 2);
                }
        }

        if (cc != 3) {
            // done reading buffer -> release it
            MBAR_ARRIVE(mb_free + buf * 8);
        } else {
            // ---- tile boundary: online softmax (scratch aliases buffer) ----
            __syncthreads();    // all warps past their ldsm of buf
            float* pmax = (float*)(smem + SM_XS + (uint32_t)buf * 32768u);
            float* psum = pmax + 512;

#pragma unroll
            for (int rb = 0; rb < 2; rb++)
#pragma unroll
                for (int rh = 0; rh < 2; rh++) {
                    float tm = -3.0e38f;
#pragma unroll
                    for (int j = 0; j < 4; j++)
                        tm = fmaxf(tm, fmaxf(acc[rb][j][2 * rh], acc[rb][j][2 * rh + 1]));
                    tm = fmaxf(tm, __shfl_xor_sync(0xffffffffu, tm, 1));
                    tm = fmaxf(tm, __shfl_xor_sync(0xffffffffu, tm, 2));
                    float ps = 0.f;
#pragma unroll
                    for (int j = 0; j < 4; j++) {
                        ps += fexp2(acc[rb][j][2 * rh] - tm);
                        ps += fexp2(acc[rb][j][2 * rh + 1] - tm);
                    }
                    ps += __shfl_xor_sync(0xffffffffu, ps, 1);
                    ps += __shfl_xor_sync(0xffffffffu, ps, 2);
                    if ((lane & 3) == 0) {
                        int rl = wr * 32 + rb * 16 + rh * 8 + g;
                        pmax[wc * 128 + rl] = tm;
                        psum[wc * 128 + rl] = ps;
                    }
                }
            // diagonal capture (raw log2-logit) -> gmem
            if (mq == (nt >> 3) && mtl == (nt & 7) && wr == wc) {
#pragma unroll
                for (int rb = 0; rb < 2; rb++)
#pragma unroll
                    for (int rh = 0; rh < 2; rh++) {
                        int cl = rb * 16 + rh * 8 + g;
                        if ((lane & 3) == ((cl & 7) >> 1))
                            g_dlog[(size_t)(b * 32 + nt) * 128 + wr * 32 + cl] =
                                acc[rb][rb * 2 + rh][2 * rh + (cl & 1)];
                    }
            }
            __syncthreads();
            // replicated combine
#pragma unroll
            for (int rb = 0; rb < 2; rb++)
#pragma unroll
                for (int rh = 0; rh < 2; rh++) {
                    int rl = wr * 32 + rb * 16 + rh * 8 + g;
                    float mn = mrun[rb][rh];
#pragma unroll
                    for (int j = 0; j < 4; j++) mn = fmaxf(mn, pmax[j * 128 + rl]);
                    float rs = rsum[rb][rh] * fexp2(mrun[rb][rh] - mn);
#pragma unroll
                    for (int j = 0; j < 4; j++)
                        rs += fexp2(pmax[j * 128 + rl] - mn) * psum[j * 128 + rl];
                    mrun[rb][rh] = mn;
                    rsum[rb][rh] = rs;
                }
#pragma unroll
            for (int i = 0; i < 2; i++)
#pragma unroll
                for (int j = 0; j < 4; j++)
#pragma unroll
                    for (int k = 0; k < 4; k++) acc[i][j][k] = 0.f;
            // scratch reads done -> release buffer for the next producer
            MBAR_ARRIVE(mb_free + buf * 8);
        }
    }

    // write partial state
    if (wc == 0 && (lane & 3) == 0) {
#pragma unroll
        for (int rb = 0; rb < 2; rb++)
#pragma unroll
            for (int rh = 0; rh < 2; rh++) {
                int rl = wr * 32 + rb * 16 + rh * 8 + g;
                g_pm[(size_t)bx * 128 + rl] = mrun[rb][rh];
                g_ps[(size_t)bx * 128 + rl] = rsum[rb][rh];
            }
    }
}

// ---------------------------------------------------------------------------
// k_final: combine 4 partials -> diag; out[b][c][n0..] = X * diag
// ---------------------------------------------------------------------------
__global__ __launch_bounds__(512) void k_final(const float* __restrict__ X,
                                               float* __restrict__ out) {
    __shared__ float sdiag[128];
    const int bx = blockIdx.x;
    const int b = bx >> 5, nt = bx & 31;
    const int n0 = nt << 7;
    const int tid = threadIdx.x;

    if (tid < 128) {
        float pm[4];
        float M = -3.0e38f;
#pragma unroll
        for (int q = 0; q < 4; q++) {
            pm[q] = g_pm[((size_t)bx * 4 + q) * 128 + tid];
            M = fmaxf(M, pm[q]);
        }
        float S = 0.f;
#pragma unroll
        for (int q = 0; q < 4; q++)
            S += g_ps[((size_t)bx * 4 + q) * 128 + tid] * fexp2(pm[q] - M);
        sdiag[tid] = fexp2(g_dlog[(size_t)bx * 128 + tid] - M) / S *
                     (1.0f / (1.0f + 1e-8f));
    }
    __syncthreads();

    const float* Xb = X + (size_t)b * CC * NN;
    float* Ob = out + (size_t)b * CC * NN;
#pragma unroll 4
    for (int t = 0; t < 16; t++) {
        int f = tid + t * 512;
        int row = f >> 5;
        int c4 = (f & 31) << 2;
        float4 v = *(const float4*)&Xb[(size_t)row * NN + n0 + c4];
        float4 dv = *(const float4*)&sdiag[c4];
        v.x *= dv.x; v.y *= dv.y; v.z *= dv.z; v.w *= dv.w;
        *(float4*)&Ob[(size_t)row * NN + n0 + c4] = v;
    }
}

// ---------------------------------------------------------------------------
extern "C" void kernel_launch(void* const* d_in, const int* in_sizes, int n_in,
                              void* d_out, int out_size) {
    const float* X  = (const float*)d_in[0];
    const float* Wq = (const float*)d_in[1];
    const float* Wk = (const float*)d_in[2];
    float* out = (float*)d_out;

    cudaFuncSetAttribute(k_Zt, cudaFuncAttributeMaxDynamicSharedMemorySize, 131072);
    cudaFuncSetAttribute(k_part, cudaFuncAttributeMaxDynamicSharedMemorySize, SM_TOTAL);

    k_prepA<<<dim3(8, 32), dim3(32, 8)>>>(Wq, Wk);
    k_prep<<<dim3(NN / 32, CC / 32, BB), dim3(32, 8)>>>(X);
    k_Zt<<<dim3(32, 2, BB), 256, 131072>>>();
    k_part<<<BB * 32 * 4, 512, SM_TOTAL>>>();
    k_final<<<BB * 32, 512>>>(X, out);
}

// round 13
// speedup vs baseline: 1.9049x; 1.0246x over previous
#include <cuda_runtime.h>
#include <cuda_bf16.h>
#include <cstdint>

#define CC 256
#define NN 4096
#define BB 8

// ---------------- device globals (no runtime allocs allowed) ----------------
static __device__ __nv_bfloat16 g_Ah[CC * CC];      // A hi  [d][c]
static __device__ __nv_bfloat16 g_Al[CC * CC];      // A lo
static __device__ __nv_bfloat16 g_Xt_hi[(size_t)BB * NN * CC];  // X^T hi [b][n][c]
static __device__ __nv_bfloat16 g_Xt_lo[(size_t)BB * NN * CC];
static __device__ __nv_bfloat16 g_Zt_hi[(size_t)BB * NN * CC];  // Z^T hi [b][n][d]
static __device__ __nv_bfloat16 g_Zt_lo[(size_t)BB * NN * CC];
// split-softmax partials: [b*32+nt][mq][row]
static __device__ float g_pm[(size_t)BB * 32 * 4 * 128];
static __device__ float g_ps[(size_t)BB * 32 * 4 * 128];
static __device__ float g_dlog[(size_t)BB * 32 * 128];

// ---------------- helpers ----------------
__device__ __forceinline__ float fexp2(float x) {
    float y;
    asm("ex2.approx.ftz.f32 %0, %1;" : "=f"(y) : "f"(x));
    return y;
}
__device__ __forceinline__ uint32_t smem_u32(const void* p) {
    uint32_t a;
    asm("{ .reg .u64 t; cvta.to.shared.u64 t, %1; cvt.u32.u64 %0, t; }" : "=r"(a) : "l"(p));
    return a;
}
#define SWZ(o) ((o) ^ (((o) >> 3) & 0x70))

#define CP16(dst, src) \
    asm volatile("cp.async.cg.shared.global [%0], [%1], 16;" :: "r"(dst), "l"(src) : "memory")
#define CP_COMMIT() asm volatile("cp.async.commit_group;" ::: "memory")
#define CP_WAIT0()  asm volatile("cp.async.wait_group 0;" ::: "memory")

// mbarrier ops
#define MBAR_INIT(a, n) \
    asm volatile("mbarrier.init.shared.b64 [%0], %1;" :: "r"(a), "r"(n) : "memory")
#define MBAR_ARRIVE(a) \
    asm volatile("mbarrier.arrive.shared.b64 _, [%0];" :: "r"(a) : "memory")
#define CP_MBAR_ARRIVE(a) \
    asm volatile("cp.async.mbarrier.arrive.noinc.shared.b64 [%0];" :: "r"(a) : "memory")
// one-shot non-blocking probe
#define MBAR_TRY(done, a, ph) \
    asm volatile("{\n\t.reg .pred p;\n\t"                                       \
        "mbarrier.try_wait.parity.acquire.cta.shared::cta.b64 p, [%1], %2;\n\t" \
        "selp.b32 %0, 1, 0, p;\n\t}" : "=r"(done) : "r"(a), "r"(ph) : "memory")
// blocking loop (use after a failed MBAR_TRY)
#define MBAR_LOOP(a, ph) \
    asm volatile("{\n\t.reg .pred P1;\n\tWL_%=:\n\t"                            \
        "mbarrier.try_wait.parity.acquire.cta.shared::cta.b64 P1, [%0], %1, 0x989680;\n\t" \
        "@P1 bra.uni WD_%=;\n\tbra.uni WL_%=;\n\tWD_%=:\n\t}"                   \
        :: "r"(a), "r"(ph) : "memory")
#define MBAR_WAIT(a, ph) do {                                                   \
    uint32_t _m = (a), _p = (ph), _d;                                           \
    MBAR_TRY(_d, _m, _p);                                                       \
    if (!_d) MBAR_LOOP(_m, _p);                                                 \
} while (0)

__device__ __forceinline__ void ldsm4(uint32_t* r, uint32_t a) {
    asm volatile("ldmatrix.sync.aligned.m8n8.x4.shared.b16 {%0,%1,%2,%3}, [%4];"
        : "=r"(r[0]), "=r"(r[1]), "=r"(r[2]), "=r"(r[3]) : "r"(a));
}
__device__ __forceinline__ void mma16816(float* d, const uint32_t* a, const uint32_t* b) {
    asm volatile("mma.sync.aligned.m16n8k16.row.col.f32.bf16.bf16.f32 "
        "{%0,%1,%2,%3}, {%4,%5,%6,%7}, {%8,%9}, {%0,%1,%2,%3};"
        : "+f"(d[0]), "+f"(d[1]), "+f"(d[2]), "+f"(d[3])
        : "r"(a[0]), "r"(a[1]), "r"(a[2]), "r"(a[3]), "r"(b[0]), "r"(b[1]));
}
__device__ __forceinline__ uint32_t pack_bf16x2(__nv_bfloat16 a, __nv_bfloat16 b) {
    return (uint32_t)__bfloat16_as_ushort(a) | ((uint32_t)__bfloat16_as_ushort(b) << 16);
}

// ---------------------------------------------------------------------------
// A[d][c] = log2e * sum_e Wq[e][c] * Wk[e][d], stored as bf16 hi/lo
// ---------------------------------------------------------------------------
__global__ void k_prepA(const float* __restrict__ Wq, const float* __restrict__ Wk) {
    const float LOG2E = 1.4426950408889634f;
    int c = blockIdx.x * 32 + threadIdx.x;
    int d = blockIdx.y * 8 + threadIdx.y;
    float s0 = 0.f, s1 = 0.f;
#pragma unroll 8
    for (int e = 0; e < CC; e += 2) {
        s0 = fmaf(Wq[e * CC + c], Wk[e * CC + d], s0);
        s1 = fmaf(Wq[(e + 1) * CC + c], Wk[(e + 1) * CC + d], s1);
    }
    float v = (s0 + s1) * LOG2E;
    __nv_bfloat16 h = __float2bfloat16(v);
    g_Ah[d * CC + c] = h;
    g_Al[d * CC + c] = __float2bfloat16(v - __bfloat162float(h));
}

// ---------------------------------------------------------------------------
// Transpose + bf16 hi/lo split: X[b][c][n] -> Xt_hi/lo[b][n][c]
// ---------------------------------------------------------------------------
__global__ __launch_bounds__(256) void k_prep(const float* __restrict__ X) {
    __shared__ float s[32][33];
    const int b = blockIdx.z, c0 = blockIdx.y * 32, n0 = blockIdx.x * 32;
    const int tx = threadIdx.x, ty = threadIdx.y;
    const float* Xb = X + (size_t)b * CC * NN;
#pragma unroll
    for (int i = 0; i < 4; i++)
        s[ty + 8 * i][tx] = Xb[(size_t)(c0 + ty + 8 * i) * NN + n0 + tx];
    __syncthreads();
    const size_t base = (size_t)b * NN * CC;
#pragma unroll
    for (int i = 0; i < 4; i++) {
        int n = n0 + ty + 8 * i;
        float v = s[tx][ty + 8 * i];
        __nv_bfloat16 h = __float2bfloat16(v);
        g_Xt_hi[base + (size_t)n * CC + c0 + tx] = h;
        g_Xt_lo[base + (size_t)n * CC + c0 + tx] =
            __float2bfloat16(v - __bfloat162float(h));
    }
}

// ---------------------------------------------------------------------------
// k_Zt: Zt[n][d] = sum_c Xt[n][c] * A[d][c]   (3-term bf16 split, mma.sync)
// ---------------------------------------------------------------------------
__global__ __launch_bounds__(256, 1) void k_Zt() {
    extern __shared__ char smem[];
    const uint32_t sb = smem_u32(smem);
    const int tid = threadIdx.x;
    const int wid = tid >> 5, lane = tid & 31;
    const int g = lane >> 2;
    const int n0 = blockIdx.x << 7;
    const int d0 = blockIdx.y << 7;
    const int b = blockIdx.z;
    const size_t bbase = (size_t)b * NN * CC;
    const char* Xsrc[2] = {(const char*)(g_Xt_hi + bbase), (const char*)(g_Xt_lo + bbase)};
    const char* Asrc[2] = {(const char*)g_Ah, (const char*)g_Al};

    const int aRow = wid * 16 + (lane & 15);
    const uint32_t aOff = (uint32_t)(aRow * 128);
    const uint32_t aSwz = (uint32_t)((aRow * 16) & 0x70);
    const int aColX = (lane >> 4) << 4;
    const int bRowOff = (lane & 7) + ((lane >> 4) & 1) * 8;
    const int bColX = ((lane >> 3) & 1) << 4;

    float acc[16][4];
#pragma unroll
    for (int i = 0; i < 16; i++)
#pragma unroll
        for (int j = 0; j < 4; j++) acc[i][j] = 0.f;

#pragma unroll
    for (int t = 0; t < 16; t++) {
        int o = tid + t * 256;
        int role = o >> 10, r = (o >> 3) & 127, j = o & 7;
        const char* src = (role < 2)
            ? Xsrc[role] + ((size_t)(n0 + r) * CC) * 2 + j * 16
            : Asrc[role - 2] + ((size_t)(d0 + r) * CC) * 2 + j * 16;
        uint32_t dst = sb + (uint32_t)role * 16384u + SWZ((uint32_t)(r * 128 + j * 16));
        CP16(dst, src);
    }
    CP_COMMIT();

#pragma unroll 1
    for (int cc = 0; cc < 4; cc++) {
        const int buf = cc & 1;
        CP_WAIT0();
        __syncthreads();
        if (cc < 3) {
            const int cn = cc + 1, bn = buf ^ 1;
#pragma unroll
            for (int t = 0; t < 16; t++) {
                int o = tid + t * 256;
                int role = o >> 10, r = (o >> 3) & 127, j = o & 7;
                const char* src = (role < 2)
                    ? Xsrc[role] + ((size_t)(n0 + r) * CC + cn * 64) * 2 + j * 16
                    : Asrc[role - 2] + ((size_t)(d0 + r) * CC + cn * 64) * 2 + j * 16;
                uint32_t dst = sb + (uint32_t)(bn * 4 + role) * 16384u +
                               SWZ((uint32_t)(r * 128 + j * 16));
                CP16(dst, src);
            }
        }
        CP_COMMIT();

        const uint32_t xh = sb + (uint32_t)(buf * 4 + 0) * 16384u;
        const uint32_t xl = xh + 16384u;
        const uint32_t ah = sb + (uint32_t)(buf * 4 + 2) * 16384u;
        const uint32_t al = ah + 16384u;
#pragma unroll
        for (int ks = 0; ks < 4; ks++) {
            const int cb = ks * 32;
            uint32_t Ah[4], Al[4];
            uint32_t aoff = aOff + (uint32_t)((cb + aColX) ^ aSwz);
            ldsm4(Ah, xh + aoff);
            ldsm4(Al, xl + aoff);
#pragma unroll
            for (int j2 = 0; j2 < 8; j2++) {
                uint32_t Bh[4], Bl[4];
                int brow = j2 * 16 + bRowOff;
                uint32_t boff = (uint32_t)(brow * 128) +
                                (uint32_t)((cb + bColX) ^ ((brow * 16) & 0x70));
                ldsm4(Bh, ah + boff);
                ldsm4(Bl, al + boff);
                mma16816(acc[j2 * 2],     Ah, Bh);
                mma16816(acc[j2 * 2 + 1], Ah, Bh + 2);
                mma16816(acc[j2 * 2],     Ah, Bl);
                mma16816(acc[j2 * 2 + 1], Ah, Bl + 2);
                mma16816(acc[j2 * 2],     Al, Bh);
                mma16816(acc[j2 * 2 + 1], Al, Bh + 2);
            }
        }
    }

    char* Zh = (char*)(g_Zt_hi + bbase);
    char* Zl = (char*)(g_Zt_lo + bbase);
#pragma unroll
    for (int h = 0; h < 2; h++) {
        int n = n0 + wid * 16 + h * 8 + g;
#pragma unroll
        for (int bt = 0; bt < 16; bt++) {
            float v0 = acc[bt][2 * h], v1 = acc[bt][2 * h + 1];
            __nv_bfloat16 h0 = __float2bfloat16(v0);
            __nv_bfloat16 h1 = __float2bfloat16(v1);
            __nv_bfloat16 l0 = __float2bfloat16(v0 - __bfloat162float(h0));
            __nv_bfloat16 l1 = __float2bfloat16(v1 - __bfloat162float(h1));
            size_t off = ((size_t)n * CC + d0 + bt * 8 + 2 * (lane & 3)) * 2;
            *(uint32_t*)(Zh + off) = pack_bf16x2(h0, h1);
            *(uint32_t*)(Zl + off) = pack_bf16x2(l0, l1);
        }
    }
}

// ---------------------------------------------------------------------------
// k_part: grid B*32*4, 512 threads, 16 warps 4x4, warp tile 32x32.
// Z persistent (128KB), X triple-buffered via mbarrier producer/consumer.
// R12 polish: (1) the consumer's full-wait is split try/produce/loop so its
// ~90cyc fast-path latency hides under the producer's cp.async issue;
// (2) per-k16 half-phase interleave: A+B_cs0 ldsm -> 12 MMA -> B_cs1 ldsm
// -> 12 MMA, shortening the ldsm->first-MMA exposure and overlapping cs1
// loads with cs0 MMAs inside each warp.
// ---------------------------------------------------------------------------
#define SM_ZS 0u
#define SM_XS 131072u
#define SM_MBAR 229376u
#define SM_TOTAL (229376 + 64)

__global__ __launch_bounds__(512, 1) void k_part() {
    extern __shared__ char smem[];
    const uint32_t sb = smem_u32(smem);
    const int tid = threadIdx.x;
    const int wid = tid >> 5, lane = tid & 31;
    const int wr = wid >> 2, wc = wid & 3;
    const int g = lane >> 2;
    const int bx = blockIdx.x;
    const int b = bx >> 7;
    const int nt = (bx >> 2) & 31;
    const int mq = bx & 3;
    const int n0 = nt << 7;
    const size_t bbase = (size_t)b * NN * CC;
    const char* Zsrc[2] = {(const char*)(g_Zt_hi + bbase), (const char*)(g_Zt_lo + bbase)};
    const char* Xsrc[2] = {(const char*)(g_Xt_hi + bbase), (const char*)(g_Xt_lo + bbase)};

    const uint32_t mb_full = sb + SM_MBAR;        // full[k] = +8k
    const uint32_t mb_free = sb + SM_MBAR + 24;   // free[k] = +24+8k

    const int aColX = (lane >> 4) << 4;
    const int bRowOff = (lane & 7) + ((lane >> 4) & 1) * 8;
    const int bColX = ((lane >> 3) & 1) << 4;

    if (tid == 0) {
#pragma unroll
        for (int k = 0; k < 3; k++) {
            MBAR_INIT(mb_full + k * 8, 512);
            MBAR_INIT(mb_free + k * 8, 512);
        }
    }
    __syncthreads();

    // prologue pre-arrivals: free[0..2] phase 0
    MBAR_ARRIVE(mb_free + 0);
    MBAR_ARRIVE(mb_free + 8);
    MBAR_ARRIVE(mb_free + 16);

    // Z (8 tiles, SW128)
#pragma unroll
    for (int t = 0; t < 16; t++) {
        int o = tid + t * 512;
        int ch = o >> 11, hs = (o >> 10) & 1, r = (o >> 3) & 127, j = o & 7;
        const char* src = Zsrc[hs] + ((size_t)(n0 + r) * CC + ch * 64) * 2 + j * 16;
        uint32_t dst = sb + SM_ZS + (uint32_t)(ch * 2 + hs) * 16384u +
                       SWZ((uint32_t)(r * 128 + j * 16));
        CP16(dst, src);
    }
    // chunk 0 -> buffer 0 (its arrive also covers the Z copies above)
    {
        const int m00 = (mq * 8) << 7;
#pragma unroll
        for (int t = 0; t < 4; t++) {
            int o = tid + t * 512;
            int hs = o >> 10, r = (o >> 3) & 127, j = o & 7;
            const char* src = Xsrc[hs] + ((size_t)(m00 + r) * CC) * 2 + j * 16;
            uint32_t dst = sb + SM_XS + (uint32_t)hs * 16384u +
                           SWZ((uint32_t)(r * 128 + j * 16));
            CP16(dst, src);
        }
        CP_MBAR_ARRIVE(mb_full + 0);
        // chunk 1 -> buffer 1
#pragma unroll
        for (int t = 0; t < 4; t++) {
            int o = tid + t * 512;
            int hs = o >> 10, r = (o >> 3) & 127, j = o & 7;
            const char* src = Xsrc[hs] + ((size_t)(m00 + r) * CC + 64) * 2 + j * 16;
            uint32_t dst = sb + SM_XS + 32768u + (uint32_t)hs * 16384u +
                           SWZ((uint32_t)(r * 128 + j * 16));
            CP16(dst, src);
        }
        CP_MBAR_ARRIVE(mb_full + 8);
    }

    float acc[2][4][4];
#pragma unroll
    for (int i = 0; i < 2; i++)
#pragma unroll
        for (int j = 0; j < 4; j++)
#pragma unroll
            for (int k = 0; k < 4; k++) acc[i][j][k] = 0.f;
    float mrun[2][2], rsum[2][2];
#pragma unroll
    for (int i = 0; i < 2; i++)
#pragma unroll
        for (int j = 0; j < 2; j++) { mrun[i][j] = -3.0e38f; rsum[i][j] = 0.f; }

#pragma unroll 1
    for (int G = 0; G < 32; G++) {
        const int cc = G & 3, mtl = G >> 2;
        const int buf = G % 3;

        // probe full[buf] non-blocking; hide its latency under the producer
        uint32_t full_done;
        MBAR_TRY(full_done, mb_full + buf * 8, (G / 3) & 1);

        // ---- producer: chunk G+2 into buffer (G+2)%3 ----
        const int Gn = G + 2;
        if (Gn < 32) {
            const int k2 = Gn % 3;
            MBAR_WAIT(mb_free + k2 * 8, (Gn / 3) & 1);
            const int ccn = Gn & 3, m0n = (mq * 8 + (Gn >> 2)) << 7;
#pragma unroll
            for (int t = 0; t < 4; t++) {
                int o = tid + t * 512;
                int hs = o >> 10, r = (o >> 3) & 127, j = o & 7;
                const char* src = Xsrc[hs] + ((size_t)(m0n + r) * CC + ccn * 64) * 2 + j * 16;
                uint32_t dst = sb + SM_XS + (uint32_t)k2 * 32768u +
                               (uint32_t)hs * 16384u + SWZ((uint32_t)(r * 128 + j * 16));
                CP16(dst, src);
            }
            CP_MBAR_ARRIVE(mb_full + k2 * 8);
        }

        // ---- consumer: complete the wait for chunk G ----
        if (!full_done) MBAR_LOOP(mb_full + buf * 8, (G / 3) & 1);

        const uint32_t zh = sb + SM_ZS + (uint32_t)(cc * 2) * 16384u;
        const uint32_t zl = zh + 16384u;
        const uint32_t xh = sb + SM_XS + (uint32_t)buf * 32768u;
        const uint32_t xl = xh + 16384u;
#pragma unroll
        for (int ks = 0; ks < 4; ks++) {
            const int cb = ks * 32;
            uint32_t Ah[2][4], Al[2][4], Bh[2][4], Bl[2][4];
            // A fragments (both rb, both halves)
#pragma unroll
            for (int rb = 0; rb < 2; rb++) {
                int row = wr * 32 + rb * 16 + (lane & 15);
                uint32_t off = (uint32_t)(row * 128) +
                               (uint32_t)((cb + aColX) ^ ((row * 16) & 0x70));
                ldsm4(Ah[rb], zh + off);
                ldsm4(Al[rb], zl + off);
            }
            // half-phase cs=0: load B0, run its 12 MMAs
            {
                int row = wc * 32 + 0 * 16 + bRowOff;
                uint32_t off = (uint32_t)(row * 128) +
                               (uint32_t)((cb + bColX) ^ ((row * 16) & 0x70));
                ldsm4(Bh[0], xh + off);
                ldsm4(Bl[0], xl + off);
            }
#pragma unroll
            for (int rb = 0; rb < 2; rb++) {
                mma16816(acc[rb][0], Ah[rb], Bh[0]);
                mma16816(acc[rb][1], Ah[rb], Bh[0] + 2);
            }
#pragma unroll
            for (int rb = 0; rb < 2; rb++) {
                mma16816(acc[rb][0], Ah[rb], Bl[0]);
                mma16816(acc[rb][1], Ah[rb], Bl[0] + 2);
            }
            // half-phase cs=1: overlap its loads with trailing cs0 MMAs
            {
                int row = wc * 32 + 1 * 16 + bRowOff;
                uint32_t off = (uint32_t)(row * 128) +
                               (uint32_t)((cb + bColX) ^ ((row * 16) & 0x70));
                ldsm4(Bh[1], xh + off);
                ldsm4(Bl[1], xl + off);
            }
#pragma unroll
            for (int rb = 0; rb < 2; rb++) {
                mma16816(acc[rb][0], Al[rb], Bh[0]);
                mma16816(acc[rb][1], Al[rb], Bh[0] + 2);
            }
#pragma unroll
            for (int rb = 0; rb < 2; rb++) {
                mma16816(acc[rb][2], Ah[rb], Bh[1]);
                mma16816(acc[rb][3], Ah[rb], Bh[1] + 2);
            }
#pragma unroll
            for (int rb = 0; rb < 2; rb++) {
                mma16816(acc[rb][2], Ah[rb], Bl[1]);
                mma16816(acc[rb][3], Ah[rb], Bl[1] + 2);
            }
#pragma unroll
            for (int rb = 0; rb < 2; rb++) {
                mma16816(acc[rb][2], Al[rb], Bh[1]);
                mma16816(acc[rb][3], Al[rb], Bh[1] + 2);
            }
        }

        if (cc != 3) {
            // done reading buffer -> release it
            MBAR_ARRIVE(mb_free + buf * 8);
        } else {
            // ---- tile boundary: online softmax (scratch aliases buffer) ----
            __syncthreads();    // all warps past their ldsm of buf
            float* pmax = (float*)(smem + SM_XS + (uint32_t)buf * 32768u);
            float* psum = pmax + 512;

#pragma unroll
            for (int rb = 0; rb < 2; rb++)
#pragma unroll
                for (int rh = 0; rh < 2; rh++) {
                    float tm = -3.0e38f;
#pragma unroll
                    for (int j = 0; j < 4; j++)
                        tm = fmaxf(tm, fmaxf(acc[rb][j][2 * rh], acc[rb][j][2 * rh + 1]));
                    tm = fmaxf(tm, __shfl_xor_sync(0xffffffffu, tm, 1));
                    tm = fmaxf(tm, __shfl_xor_sync(0xffffffffu, tm, 2));
                    float ps = 0.f;
#pragma unroll
                    for (int j = 0; j < 4; j++) {
                        ps += fexp2(acc[rb][j][2 * rh] - tm);
                        ps += fexp2(acc[rb][j][2 * rh + 1] - tm);
                    }
                    ps += __shfl_xor_sync(0xffffffffu, ps, 1);
                    ps += __shfl_xor_sync(0xffffffffu, ps, 2);
                    if ((lane & 3) == 0) {
                        int rl = wr * 32 + rb * 16 + rh * 8 + g;
                        pmax[wc * 128 + rl] = tm;
                        psum[wc * 128 + rl] = ps;
                    }
                }
            // diagonal capture (raw log2-logit) -> gmem
            if (mq == (nt >> 3) && mtl == (nt & 7) && wr == wc) {
#pragma unroll
                for (int rb = 0; rb < 2; rb++)
#pragma unroll
                    for (int rh = 0; rh < 2; rh++) {
                        int cl = rb * 16 + rh * 8 + g;
                        if ((lane & 3) == ((cl & 7) >> 1))
                            g_dlog[(size_t)(b * 32 + nt) * 128 + wr * 32 + cl] =
                                acc[rb][rb * 2 + rh][2 * rh + (cl & 1)];
                    }
            }
            __syncthreads();
            // replicated combine
#pragma unroll
            for (int rb = 0; rb < 2; rb++)
#pragma unroll
                for (int rh = 0; rh < 2; rh++) {
                    int rl = wr * 32 + rb * 16 + rh * 8 + g;
                    float mn = mrun[rb][rh];
#pragma unroll
                    for (int j = 0; j < 4; j++) mn = fmaxf(mn, pmax[j * 128 + rl]);
                    float rs = rsum[rb][rh] * fexp2(mrun[rb][rh] - mn);
#pragma unroll
                    for (int j = 0; j < 4; j++)
                        rs += fexp2(pmax[j * 128 + rl] - mn) * psum[j * 128 + rl];
                    mrun[rb][rh] = mn;
                    rsum[rb][rh] = rs;
                }
#pragma unroll
            for (int i = 0; i < 2; i++)
#pragma unroll
                for (int j = 0; j < 4; j++)
#pragma unroll
                    for (int k = 0; k < 4; k++) acc[i][j][k] = 0.f;
            // scratch reads done -> release buffer for the next producer
            MBAR_ARRIVE(mb_free + buf * 8);
        }
    }

    // write partial state
    if (wc == 0 && (lane & 3) == 0) {
#pragma unroll
        for (int rb = 0; rb < 2; rb++)
#pragma unroll
            for (int rh = 0; rh < 2; rh++) {
                int rl = wr * 32 + rb * 16 + rh * 8 + g;
                g_pm[(size_t)bx * 128 + rl] = mrun[rb][rh];
                g_ps[(size_t)bx * 128 + rl] = rsum[rb][rh];
            }
    }
}

// ---------------------------------------------------------------------------
// k_final: combine 4 partials -> diag; out[b][c][n0..] = X * diag
// ---------------------------------------------------------------------------
__global__ __launch_bounds__(512) void k_final(const float* __restrict__ X,
                                               float* __restrict__ out) {
    __shared__ float sdiag[128];
    const int bx = blockIdx.x;
    const int b = bx >> 5, nt = bx & 31;
    const int n0 = nt << 7;
    const int tid = threadIdx.x;

    if (tid < 128) {
        float pm[4];
        float M = -3.0e38f;
#pragma unroll
        for (int q = 0; q < 4; q++) {
            pm[q] = g_pm[((size_t)bx * 4 + q) * 128 + tid];
            M = fmaxf(M, pm[q]);
        }
        float S = 0.f;
#pragma unroll
        for (int q = 0; q < 4; q++)
            S += g_ps[((size_t)bx * 4 + q) * 128 + tid] * fexp2(pm[q] - M);
        sdiag[tid] = fexp2(g_dlog[(size_t)bx * 128 + tid] - M) / S *
                     (1.0f / (1.0f + 1e-8f));
    }
    __syncthreads();

    const float* Xb = X + (size_t)b * CC * NN;
    float* Ob = out + (size_t)b * CC * NN;
#pragma unroll 4
    for (int t = 0; t < 16; t++) {
        int f = tid + t * 512;
        int row = f >> 5;
        int c4 = (f & 31) << 2;
        float4 v = *(const float4*)&Xb[(size_t)row * NN + n0 + c4];
        float4 dv = *(const float4*)&sdiag[c4];
        v.x *= dv.x; v.y *= dv.y; v.z *= dv.z; v.w *= dv.w;
        *(float4*)&Ob[(size_t)row * NN + n0 + c4] = v;
    }
}

// ---------------------------------------------------------------------------
extern "C" void kernel_launch(void* const* d_in, const int* in_sizes, int n_in,
                              void* d_out, int out_size) {
    const float* X  = (const float*)d_in[0];
    const float* Wq = (const float*)d_in[1];
    const float* Wk = (const float*)d_in[2];
    float* out = (float*)d_out;

    cudaFuncSetAttribute(k_Zt, cudaFuncAttributeMaxDynamicSharedMemorySize, 131072);
    cudaFuncSetAttribute(k_part, cudaFuncAttributeMaxDynamicSharedMemorySize, SM_TOTAL);

    k_prepA<<<dim3(8, 32), dim3(32, 8)>>>(Wq, Wk);
    k_prep<<<dim3(NN / 32, CC / 32, BB), dim3(32, 8)>>>(X);
    k_Zt<<<dim3(32, 2, BB), 256, 131072>>>();
    k_part<<<BB * 32 * 4, 512, SM_TOTAL>>>();
    k_final<<<BB * 32, 512>>>(X, out);
}